// round 2
// baseline (speedup 1.0000x reference)
#include <cuda_runtime.h>
#include <math.h>

#define BB 2
#define SS 4096
#define DD 512
#define HH 8
#define DH 64
#define M_ROWS (BB*SS)   // 8192
#define PAD 68

// Scratch (allocation-free rule: __device__ globals)
__device__ float g_qp[(size_t)BB*HH*SS*DH];   // [B,H,S,d]
__device__ float g_kp[(size_t)BB*HH*SS*DH];
__device__ float g_vp[(size_t)BB*HH*SS*DH];
__device__ float g_attn[(size_t)M_ROWS*DD];   // [B*S, D]

// ---------------------------------------------------------------------------
// Projection GEMM: out = A[M x 512] @ W[512 x 512] + bias
// 64x64 tile, BK=16, 256 threads, 4x4 register blocking.
// SCATTER=true writes into [B,H,S,d] split-heads layout; else row-major [M,512].
// ---------------------------------------------------------------------------
template<bool SCATTER>
__global__ __launch_bounds__(256) void proj_gemm(
    const float* __restrict__ A, const float* __restrict__ W,
    const float* __restrict__ bias, float* __restrict__ out)
{
    __shared__ float As[16][68];   // transposed: As[k][m]
    __shared__ float Bs[16][68];   // Bs[k][n]

    const int tid = threadIdx.x;
    const int tx = tid & 15, ty = tid >> 4;
    const int n0 = blockIdx.x * 64;
    const int m0 = blockIdx.y * 64;

    const int arow = tid >> 2;          // 0..63
    const int ak4  = (tid & 3) * 4;     // 0,4,8,12
    const int brow = tid >> 4;          // 0..15
    const int bcol = (tid & 15) * 4;    // 0..60

    float acc[4][4] = {};

    for (int k0 = 0; k0 < 512; k0 += 16) {
        float4 av = *(const float4*)&A[(size_t)(m0 + arow) * 512 + k0 + ak4];
        As[ak4 + 0][arow] = av.x;
        As[ak4 + 1][arow] = av.y;
        As[ak4 + 2][arow] = av.z;
        As[ak4 + 3][arow] = av.w;
        *(float4*)&Bs[brow][bcol] =
            *(const float4*)&W[(size_t)(k0 + brow) * 512 + n0 + bcol];
        __syncthreads();

#pragma unroll
        for (int k = 0; k < 16; ++k) {
            float4 a = *(const float4*)&As[k][ty * 4];
            float4 b = *(const float4*)&Bs[k][tx * 4];
            float ar[4] = {a.x, a.y, a.z, a.w};
            float br[4] = {b.x, b.y, b.z, b.w};
#pragma unroll
            for (int i = 0; i < 4; ++i)
#pragma unroll
                for (int j = 0; j < 4; ++j)
                    acc[i][j] = fmaf(ar[i], br[j], acc[i][j]);
        }
        __syncthreads();
    }

#pragma unroll
    for (int i = 0; i < 4; ++i) {
        int m = m0 + ty * 4 + i;
#pragma unroll
        for (int j = 0; j < 4; ++j) {
            int c = n0 + tx * 4 + j;
            float v = acc[i][j] + bias[c];
            if (SCATTER) {
                int b = m / SS, s = m % SS;
                int h = c / DH, dd = c % DH;
                out[(((size_t)b * HH + h) * SS + s) * DH + dd] = v;
            } else {
                out[(size_t)m * 512 + c] = v;
            }
        }
    }
}

// ---------------------------------------------------------------------------
// Flash attention: per block = one (b,h) and 64 q-rows. Loop over 64-row KV
// tiles with online softmax. No 1/sqrt(d) scaling (matches reference).
// ---------------------------------------------------------------------------
__global__ __launch_bounds__(256) void attn_kernel(
    const float* __restrict__ qp, const float* __restrict__ kp,
    const float* __restrict__ vp, const float* __restrict__ mask,
    float* __restrict__ out)
{
    extern __shared__ float sm[];
    float* Qs = sm;                 // [64][PAD]  (row, k)
    float* Ks = Qs + 64 * PAD;      // [64][PAD]  (kv row, k)
    float* Vt = Ks + 64 * PAD;      // [64][PAD]  transposed: (dcol, kv row)
    float* Ps = Vt + 64 * PAD;      // [64][PAD]  probabilities
    float* Ms = Ps + 64 * PAD;      // [64] mask values

    const int tid = threadIdx.x;
    const int tx = tid & 15, ty = tid >> 4;
    const int q0 = blockIdx.x * 64;
    const int h  = blockIdx.y;
    const int b  = blockIdx.z;

    const float* qb = qp + (((size_t)b * HH + h) * SS) * DH;
    const float* kb = kp + (((size_t)b * HH + h) * SS) * DH;
    const float* vb = vp + (((size_t)b * HH + h) * SS) * DH;

    // Load Q tile (64x64)
    {
        int row = tid >> 2;
        int c0  = (tid & 3) * 4;
#pragma unroll
        for (int i = 0; i < 4; ++i) {
            float4 v = *(const float4*)&qb[(size_t)(q0 + row) * DH + c0 + 16 * i];
            *(float4*)&Qs[row * PAD + c0 + 16 * i] = v;
        }
    }

    float m_run[4], l_run[4], o[4][4];
#pragma unroll
    for (int i = 0; i < 4; ++i) {
        m_run[i] = -1e30f; l_run[i] = 0.f;
#pragma unroll
        for (int j = 0; j < 4; ++j) o[i][j] = 0.f;
    }

    for (int kt = 0; kt < SS; kt += 64) {
        __syncthreads();  // previous PV/P users done before overwrite
        {
            int row = tid >> 2;
            int c0  = (tid & 3) * 4;
#pragma unroll
            for (int i = 0; i < 4; ++i) {
                float4 v = *(const float4*)&kb[(size_t)(kt + row) * DH + c0 + 16 * i];
                *(float4*)&Ks[row * PAD + c0 + 16 * i] = v;
                float4 w = *(const float4*)&vb[(size_t)(kt + row) * DH + c0 + 16 * i];
                Vt[(c0 + 16 * i + 0) * PAD + row] = w.x;
                Vt[(c0 + 16 * i + 1) * PAD + row] = w.y;
                Vt[(c0 + 16 * i + 2) * PAD + row] = w.z;
                Vt[(c0 + 16 * i + 3) * PAD + row] = w.w;
            }
            if (tid < 64) Ms[tid] = mask[(size_t)b * SS + kt + tid];
        }
        __syncthreads();

        // S = Q K^T  (4x4 per thread)
        float sacc[4][4] = {};
#pragma unroll
        for (int k = 0; k < DH; k += 4) {
            float4 qv[4], kv[4];
#pragma unroll
            for (int i = 0; i < 4; ++i)
                qv[i] = *(const float4*)&Qs[(ty * 4 + i) * PAD + k];
#pragma unroll
            for (int j = 0; j < 4; ++j)
                kv[j] = *(const float4*)&Ks[(tx * 4 + j) * PAD + k];
#pragma unroll
            for (int i = 0; i < 4; ++i)
#pragma unroll
                for (int j = 0; j < 4; ++j) {
                    sacc[i][j] = fmaf(qv[i].x, kv[j].x, sacc[i][j]);
                    sacc[i][j] = fmaf(qv[i].y, kv[j].y, sacc[i][j]);
                    sacc[i][j] = fmaf(qv[i].z, kv[j].z, sacc[i][j]);
                    sacc[i][j] = fmaf(qv[i].w, kv[j].w, sacc[i][j]);
                }
        }
        // mask: score += mask[k]*-1e9
#pragma unroll
        for (int j = 0; j < 4; ++j) {
            float mval = Ms[tx * 4 + j] * -1e9f;
#pragma unroll
            for (int i = 0; i < 4; ++i) sacc[i][j] += mval;
        }
        // online softmax per q-row (row spread over 16 consecutive lanes)
#pragma unroll
        for (int i = 0; i < 4; ++i) {
            float mx = sacc[i][0];
#pragma unroll
            for (int j = 1; j < 4; ++j) mx = fmaxf(mx, sacc[i][j]);
#pragma unroll
            for (int off = 1; off < 16; off <<= 1)
                mx = fmaxf(mx, __shfl_xor_sync(0xffffffffu, mx, off));
            float m_new = fmaxf(m_run[i], mx);
            float corr  = __expf(m_run[i] - m_new);
            m_run[i] = m_new;
            float rsum = 0.f;
#pragma unroll
            for (int j = 0; j < 4; ++j) {
                float p = __expf(sacc[i][j] - m_new);
                sacc[i][j] = p;
                rsum += p;
            }
#pragma unroll
            for (int off = 1; off < 16; off <<= 1)
                rsum += __shfl_xor_sync(0xffffffffu, rsum, off);
            l_run[i] = l_run[i] * corr + rsum;
#pragma unroll
            for (int j = 0; j < 4; ++j) o[i][j] *= corr;
        }
        // stage P
#pragma unroll
        for (int i = 0; i < 4; ++i)
#pragma unroll
            for (int j = 0; j < 4; ++j)
                Ps[(ty * 4 + i) * PAD + tx * 4 + j] = sacc[i][j];
        __syncthreads();

        // O += P @ V   (Vt is [dcol][kvrow])
#pragma unroll
        for (int j = 0; j < 64; j += 4) {
            float4 pv[4], vv[4];
#pragma unroll
            for (int i = 0; i < 4; ++i)
                pv[i] = *(const float4*)&Ps[(ty * 4 + i) * PAD + j];
#pragma unroll
            for (int c = 0; c < 4; ++c)
                vv[c] = *(const float4*)&Vt[(tx * 4 + c) * PAD + j];
#pragma unroll
            for (int i = 0; i < 4; ++i)
#pragma unroll
                for (int c = 0; c < 4; ++c) {
                    o[i][c] = fmaf(pv[i].x, vv[c].x, o[i][c]);
                    o[i][c] = fmaf(pv[i].y, vv[c].y, o[i][c]);
                    o[i][c] = fmaf(pv[i].z, vv[c].z, o[i][c]);
                    o[i][c] = fmaf(pv[i].w, vv[c].w, o[i][c]);
                }
        }
    }

    // epilogue: normalize and write merged-head layout [B,S,D]
#pragma unroll
    for (int i = 0; i < 4; ++i) {
        float inv = 1.0f / l_run[i];
        int srow = q0 + ty * 4 + i;
#pragma unroll
        for (int c = 0; c < 4; ++c) {
            out[((size_t)b * SS + srow) * DD + h * DH + tx * 4 + c] = o[i][c] * inv;
        }
    }
}

// ---------------------------------------------------------------------------
extern "C" void kernel_launch(void* const* d_in, const int* in_sizes, int n_in,
                              void* d_out, int out_size)
{
    (void)in_sizes; (void)n_in; (void)out_size;
    const float* q    = (const float*)d_in[0];
    const float* k    = (const float*)d_in[1];
    const float* v    = (const float*)d_in[2];
    const float* mask = (const float*)d_in[3];
    const float* wq   = (const float*)d_in[4];
    const float* bq   = (const float*)d_in[5];
    const float* wk   = (const float*)d_in[6];
    const float* bk   = (const float*)d_in[7];
    const float* wv   = (const float*)d_in[8];
    const float* bv   = (const float*)d_in[9];
    const float* wo   = (const float*)d_in[10];
    const float* bo   = (const float*)d_in[11];
    float* out = (float*)d_out;

    float *qp, *kp, *vp, *attn;
    cudaGetSymbolAddress((void**)&qp,   g_qp);
    cudaGetSymbolAddress((void**)&kp,   g_kp);
    cudaGetSymbolAddress((void**)&vp,   g_vp);
    cudaGetSymbolAddress((void**)&attn, g_attn);

    static int smem_set = 0;
    const int ATTN_SMEM = (4 * 64 * PAD + 64) * (int)sizeof(float);  // 69,888 B
    if (!smem_set) {
        cudaFuncSetAttribute(attn_kernel,
                             cudaFuncAttributeMaxDynamicSharedMemorySize,
                             ATTN_SMEM);
        smem_set = 1;
    }

    dim3 gproj(DD / 64, M_ROWS / 64);  // (8, 128)
    proj_gemm<true><<<gproj, 256>>>(q, wq, bq, qp);
    proj_gemm<true><<<gproj, 256>>>(k, wk, bk, kp);
    proj_gemm<true><<<gproj, 256>>>(v, wv, bv, vp);

    dim3 gattn(SS / 64, HH, BB);       // (64, 8, 2)
    attn_kernel<<<gattn, 256, ATTN_SMEM>>>(qp, kp, vp, mask, attn);

    proj_gemm<false><<<gproj, 256>>>(attn, wo, bo, out);
}

// round 3
// speedup vs baseline: 1.9723x; 1.9723x over previous
#include <cuda_runtime.h>
#include <math.h>

#define BB 2
#define SS 4096
#define DD 512
#define HH 8
#define DH 64
#define M_ROWS (BB*SS)   // 8192

// attention tiles
#define TQ 128
#define TK 128
#define PADK 68     // Q/K/V row pitch (words)
#define PADP 132    // P row pitch (words)

// Scratch (allocation-free rule: __device__ globals)
__device__ float g_qp[(size_t)BB*HH*SS*DH];   // [B,H,S,d]
__device__ float g_kp[(size_t)BB*HH*SS*DH];
__device__ float g_vp[(size_t)BB*HH*SS*DH];
__device__ float g_attn[(size_t)M_ROWS*DD];   // [B*S, D]

// ---------------------------------------------------------------------------
// Projection GEMM: out = A[M x 512] @ W[512 x 512] + bias
// 64x64 tile, BK=16, 256 threads, 4x4 register blocking.
// ---------------------------------------------------------------------------
template<bool SCATTER>
__global__ __launch_bounds__(256) void proj_gemm(
    const float* __restrict__ A, const float* __restrict__ W,
    const float* __restrict__ bias, float* __restrict__ out)
{
    __shared__ float As[16][68];   // transposed: As[k][m]
    __shared__ float Bs[16][68];   // Bs[k][n]

    const int tid = threadIdx.x;
    const int tx = tid & 15, ty = tid >> 4;
    const int n0 = blockIdx.x * 64;
    const int m0 = blockIdx.y * 64;

    const int arow = tid >> 2;
    const int ak4  = (tid & 3) * 4;
    const int brow = tid >> 4;
    const int bcol = (tid & 15) * 4;

    float acc[4][4] = {};

    for (int k0 = 0; k0 < 512; k0 += 16) {
        float4 av = *(const float4*)&A[(size_t)(m0 + arow) * 512 + k0 + ak4];
        As[ak4 + 0][arow] = av.x;
        As[ak4 + 1][arow] = av.y;
        As[ak4 + 2][arow] = av.z;
        As[ak4 + 3][arow] = av.w;
        *(float4*)&Bs[brow][bcol] =
            *(const float4*)&W[(size_t)(k0 + brow) * 512 + n0 + bcol];
        __syncthreads();

#pragma unroll
        for (int k = 0; k < 16; ++k) {
            float4 a = *(const float4*)&As[k][ty * 4];
            float4 b = *(const float4*)&Bs[k][tx * 4];
            float ar[4] = {a.x, a.y, a.z, a.w};
            float br[4] = {b.x, b.y, b.z, b.w};
#pragma unroll
            for (int i = 0; i < 4; ++i)
#pragma unroll
                for (int j = 0; j < 4; ++j)
                    acc[i][j] = fmaf(ar[i], br[j], acc[i][j]);
        }
        __syncthreads();
    }

#pragma unroll
    for (int i = 0; i < 4; ++i) {
        int m = m0 + ty * 4 + i;
#pragma unroll
        for (int j = 0; j < 4; ++j) {
            int c = n0 + tx * 4 + j;
            float v = acc[i][j] + bias[c];
            if (SCATTER) {
                int b = m / SS, s = m % SS;
                int h = c / DH, dd = c % DH;
                out[(((size_t)b * HH + h) * SS + s) * DH + dd] = v;
            } else {
                out[(size_t)m * 512 + c] = v;
            }
        }
    }
}

// ---------------------------------------------------------------------------
// Flash attention v2: 128 q-rows x 128 kv-rows per iteration, 256 threads.
// Thread (tx=tid&15, ty=tid>>4): q-rows ty*8+i (i<8); kv-cols tx+16*jj (jj<8,
// strided to avoid smem bank conflicts); O dims tx*4+cc (cc<4).
// ---------------------------------------------------------------------------
__global__ __launch_bounds__(256, 1) void attn_kernel(
    const float* __restrict__ qp, const float* __restrict__ kp,
    const float* __restrict__ vp, const float* __restrict__ mask,
    float* __restrict__ out)
{
    extern __shared__ float sm[];
    float* Qs = sm;                    // [TQ][PADK]
    float* Ks = Qs + TQ * PADK;        // [TK][PADK]
    float* Vs = Ks + TK * PADK;        // [TK][PADK]   row-major (kv row, dim)
    float* Ps = Vs + TK * PADK;        // [TQ][PADP]
    float* Ms = Ps + TQ * PADP;        // [TK]

    const int tid = threadIdx.x;
    const int tx = tid & 15, ty = tid >> 4;
    const int q0 = blockIdx.x * TQ;
    const int h  = blockIdx.y;
    const int b  = blockIdx.z;

    const float* qb = qp + (((size_t)b * HH + h) * SS) * DH;
    const float* kb = kp + (((size_t)b * HH + h) * SS) * DH;
    const float* vb = vp + (((size_t)b * HH + h) * SS) * DH;

    // Load Q tile (128x64): each thread 32 floats
    {
        int row = tid >> 1;
        int c0  = (tid & 1) * 32;
#pragma unroll
        for (int i = 0; i < 8; ++i) {
            float4 v = *(const float4*)&qb[(size_t)(q0 + row) * DH + c0 + 4 * i];
            *(float4*)&Qs[row * PADK + c0 + 4 * i] = v;
        }
    }

    float m_run[8], l_run[8], o[8][4];
#pragma unroll
    for (int i = 0; i < 8; ++i) {
        m_run[i] = -1e30f; l_run[i] = 0.f;
#pragma unroll
        for (int c = 0; c < 4; ++c) o[i][c] = 0.f;
    }

    for (int kt = 0; kt < SS; kt += TK) {
        __syncthreads();   // prev iter PV done before overwriting Ks/Vs/Ps
        {
            int row = tid >> 1;
            int c0  = (tid & 1) * 32;
#pragma unroll
            for (int i = 0; i < 8; ++i) {
                float4 v = *(const float4*)&kb[(size_t)(kt + row) * DH + c0 + 4 * i];
                *(float4*)&Ks[row * PADK + c0 + 4 * i] = v;
                float4 w = *(const float4*)&vb[(size_t)(kt + row) * DH + c0 + 4 * i];
                *(float4*)&Vs[row * PADK + c0 + 4 * i] = w;
            }
            if (tid < TK) Ms[tid] = mask[(size_t)b * SS + kt + tid];
        }
        __syncthreads();

        // ---- S = Q K^T : sacc[i][jj] for q-row ty*8+i, kv-col tx+16*jj ----
        float sacc[8][8] = {};
#pragma unroll
        for (int k = 0; k < DH; k += 4) {
            float4 qv[8], kv[8];
#pragma unroll
            for (int i = 0; i < 8; ++i)
                qv[i] = *(const float4*)&Qs[(ty * 8 + i) * PADK + k];
#pragma unroll
            for (int jj = 0; jj < 8; ++jj)
                kv[jj] = *(const float4*)&Ks[(tx + 16 * jj) * PADK + k];
#pragma unroll
            for (int i = 0; i < 8; ++i)
#pragma unroll
                for (int jj = 0; jj < 8; ++jj) {
                    sacc[i][jj] = fmaf(qv[i].x, kv[jj].x, sacc[i][jj]);
                    sacc[i][jj] = fmaf(qv[i].y, kv[jj].y, sacc[i][jj]);
                    sacc[i][jj] = fmaf(qv[i].z, kv[jj].z, sacc[i][jj]);
                    sacc[i][jj] = fmaf(qv[i].w, kv[jj].w, sacc[i][jj]);
                }
        }

        // mask add
#pragma unroll
        for (int jj = 0; jj < 8; ++jj) {
            float mval = Ms[tx + 16 * jj] * -1e9f;
#pragma unroll
            for (int i = 0; i < 8; ++i) sacc[i][jj] += mval;
        }

        // online softmax per q-row (row = 16 lanes of same ty)
#pragma unroll
        for (int i = 0; i < 8; ++i) {
            float mx = sacc[i][0];
#pragma unroll
            for (int jj = 1; jj < 8; ++jj) mx = fmaxf(mx, sacc[i][jj]);
#pragma unroll
            for (int off = 1; off < 16; off <<= 1)
                mx = fmaxf(mx, __shfl_xor_sync(0xffffffffu, mx, off));
            float m_new = fmaxf(m_run[i], mx);
            float corr  = __expf(m_run[i] - m_new);
            m_run[i] = m_new;
            float rsum = 0.f;
#pragma unroll
            for (int jj = 0; jj < 8; ++jj) {
                float p = __expf(sacc[i][jj] - m_new);
                sacc[i][jj] = p;
                rsum += p;
            }
#pragma unroll
            for (int off = 1; off < 16; off <<= 1)
                rsum += __shfl_xor_sync(0xffffffffu, rsum, off);
            l_run[i] = l_run[i] * corr + rsum;
#pragma unroll
            for (int c = 0; c < 4; ++c) o[i][c] *= corr;
        }

        // stage P (scalar stores, stride-1 across tx: conflict-free)
#pragma unroll
        for (int i = 0; i < 8; ++i)
#pragma unroll
            for (int jj = 0; jj < 8; ++jj)
                Ps[(ty * 8 + i) * PADP + tx + 16 * jj] = sacc[i][jj];
        __syncthreads();

        // ---- O += P @ V : o[i][cc] for dims tx*4+cc ----
#pragma unroll 4
        for (int j = 0; j < TK; j += 4) {
            float4 pv[8], vv[4];
#pragma unroll
            for (int i = 0; i < 8; ++i)
                pv[i] = *(const float4*)&Ps[(ty * 8 + i) * PADP + j];
#pragma unroll
            for (int jj = 0; jj < 4; ++jj)
                vv[jj] = *(const float4*)&Vs[(j + jj) * PADK + tx * 4];
#pragma unroll
            for (int i = 0; i < 8; ++i) {
                o[i][0] = fmaf(pv[i].x, vv[0].x, o[i][0]);
                o[i][1] = fmaf(pv[i].x, vv[0].y, o[i][1]);
                o[i][2] = fmaf(pv[i].x, vv[0].z, o[i][2]);
                o[i][3] = fmaf(pv[i].x, vv[0].w, o[i][3]);
                o[i][0] = fmaf(pv[i].y, vv[1].x, o[i][0]);
                o[i][1] = fmaf(pv[i].y, vv[1].y, o[i][1]);
                o[i][2] = fmaf(pv[i].y, vv[1].z, o[i][2]);
                o[i][3] = fmaf(pv[i].y, vv[1].w, o[i][3]);
                o[i][0] = fmaf(pv[i].z, vv[2].x, o[i][0]);
                o[i][1] = fmaf(pv[i].z, vv[2].y, o[i][1]);
                o[i][2] = fmaf(pv[i].z, vv[2].z, o[i][2]);
                o[i][3] = fmaf(pv[i].z, vv[2].w, o[i][3]);
                o[i][0] = fmaf(pv[i].w, vv[3].x, o[i][0]);
                o[i][1] = fmaf(pv[i].w, vv[3].y, o[i][1]);
                o[i][2] = fmaf(pv[i].w, vv[3].z, o[i][2]);
                o[i][3] = fmaf(pv[i].w, vv[3].w, o[i][3]);
            }
        }
    }

    // epilogue: normalize, write merged-head [B,S,D]
#pragma unroll
    for (int i = 0; i < 8; ++i) {
        float inv = 1.0f / l_run[i];
        int srow = q0 + ty * 8 + i;
#pragma unroll
        for (int c = 0; c < 4; ++c)
            out[((size_t)b * SS + srow) * DD + h * DH + tx * 4 + c] = o[i][c] * inv;
    }
}

// ---------------------------------------------------------------------------
extern "C" void kernel_launch(void* const* d_in, const int* in_sizes, int n_in,
                              void* d_out, int out_size)
{
    (void)in_sizes; (void)n_in; (void)out_size;
    const float* q    = (const float*)d_in[0];
    const float* k    = (const float*)d_in[1];
    const float* v    = (const float*)d_in[2];
    const float* mask = (const float*)d_in[3];
    const float* wq   = (const float*)d_in[4];
    const float* bq   = (const float*)d_in[5];
    const float* wk   = (const float*)d_in[6];
    const float* bk   = (const float*)d_in[7];
    const float* wv   = (const float*)d_in[8];
    const float* bv   = (const float*)d_in[9];
    const float* wo   = (const float*)d_in[10];
    const float* bo   = (const float*)d_in[11];
    float* out = (float*)d_out;

    float *qp, *kp, *vp, *attn;
    cudaGetSymbolAddress((void**)&qp,   g_qp);
    cudaGetSymbolAddress((void**)&kp,   g_kp);
    cudaGetSymbolAddress((void**)&vp,   g_vp);
    cudaGetSymbolAddress((void**)&attn, g_attn);

    static int smem_set = 0;
    const int ATTN_SMEM =
        (3 * TQ * PADK + TQ * PADP + TK) * (int)sizeof(float);  // 173,056 B
    if (!smem_set) {
        cudaFuncSetAttribute(attn_kernel,
                             cudaFuncAttributeMaxDynamicSharedMemorySize,
                             ATTN_SMEM);
        smem_set = 1;
    }

    dim3 gproj(DD / 64, M_ROWS / 64);  // (8, 128)
    proj_gemm<true><<<gproj, 256>>>(q, wq, bq, qp);
    proj_gemm<true><<<gproj, 256>>>(k, wk, bk, kp);
    proj_gemm<true><<<gproj, 256>>>(v, wv, bv, vp);

    dim3 gattn(SS / TQ, HH, BB);       // (32, 8, 2)
    attn_kernel<<<gattn, 256, ATTN_SMEM>>>(qp, kp, vp, mask, attn);

    proj_gemm<false><<<gproj, 256>>>(attn, wo, bo, out);
}

// round 6
// speedup vs baseline: 3.4454x; 1.7469x over previous
#include <cuda_runtime.h>
#include <cuda_bf16.h>
#include <math.h>

#define BB 2
#define SS 4096
#define DD 512
#define HH 8
#define DH 64
#define M_ROWS (BB*SS)   // 8192

#define TQ 128
#define TK 128
#define KPITCH 72        // K smem pitch in bf16 elems
#define VPITCH 136       // Vt smem pitch in bf16 elems

typedef __nv_bfloat16 bf;

// Scratch (allocation-free rule: __device__ globals). [B,H,S,d] layout.
__device__ bf g_qhi[(size_t)BB*HH*SS*DH];
__device__ bf g_qlo[(size_t)BB*HH*SS*DH];
__device__ bf g_khi[(size_t)BB*HH*SS*DH];
__device__ bf g_klo[(size_t)BB*HH*SS*DH];
__device__ bf g_vhi[(size_t)BB*HH*SS*DH];
__device__ bf g_vlo[(size_t)BB*HH*SS*DH];
__device__ float g_attn[(size_t)M_ROWS*DD];   // [B*S, D]

// ---------------------------------------------------------------------------
// fast exp on FMA/ALU pipes (no MUFU). Valid for softmax args (x <= 0-ish).
// ---------------------------------------------------------------------------
__device__ __forceinline__ float fexp(float x)
{
    float y  = fmaxf(x, -80.0f) * 1.44269504f;     // log2(e)
    float yn = y + 12582912.0f;                    // 1.5*2^23 round-to-int
    float nf = yn - 12582912.0f;
    float f  = y - nf;                             // f in [-0.5, 0.5]
    int   sc = (__float_as_int(yn) - 0x4B400000 + 127) << 23;  // 2^n bits
    float p  = 1.3333558e-3f;
    p = fmaf(p, f, 9.6181291e-3f);
    p = fmaf(p, f, 5.5504109e-2f);
    p = fmaf(p, f, 2.4022651e-1f);
    p = fmaf(p, f, 6.9314718e-1f);
    p = fmaf(p, f, 1.0f);
    return __int_as_float(sc) * p;
}

__device__ __forceinline__ void mma_bf16(float* c, const unsigned* a,
                                         unsigned b0, unsigned b1)
{
    asm("mma.sync.aligned.m16n8k16.row.col.f32.bf16.bf16.f32 "
        "{%0,%1,%2,%3},{%4,%5,%6,%7},{%8,%9},{%0,%1,%2,%3};"
        : "+f"(c[0]), "+f"(c[1]), "+f"(c[2]), "+f"(c[3])
        : "r"(a[0]), "r"(a[1]), "r"(a[2]), "r"(a[3]), "r"(b0), "r"(b1));
}

__device__ __forceinline__ unsigned pack_bf2(bf a, bf b)
{
    __nv_bfloat162 t = __halves2bfloat162(a, b);   // a -> low, b -> high
    return *(unsigned*)&t;
}

// ---------------------------------------------------------------------------
// Projection GEMM with split-bf16 scatter output (for Q/K/V).
// out = A[M x 512] @ W + bias, written as hi/lo bf16 in [B,H,S,d].
// ---------------------------------------------------------------------------
__global__ __launch_bounds__(256) void proj_gemm_split(
    const float* __restrict__ A, const float* __restrict__ W,
    const float* __restrict__ bias, bf* __restrict__ ohi, bf* __restrict__ olo)
{
    __shared__ float As[16][68];
    __shared__ float Bs[16][68];

    const int tid = threadIdx.x;
    const int tx = tid & 15, ty = tid >> 4;
    const int n0 = blockIdx.x * 64;
    const int m0 = blockIdx.y * 64;

    const int arow = tid >> 2;
    const int ak4  = (tid & 3) * 4;
    const int brow = tid >> 4;
    const int bcol = (tid & 15) * 4;

    float acc[4][4] = {};

    for (int k0 = 0; k0 < 512; k0 += 16) {
        float4 av = *(const float4*)&A[(size_t)(m0 + arow) * 512 + k0 + ak4];
        As[ak4 + 0][arow] = av.x;
        As[ak4 + 1][arow] = av.y;
        As[ak4 + 2][arow] = av.z;
        As[ak4 + 3][arow] = av.w;
        *(float4*)&Bs[brow][bcol] =
            *(const float4*)&W[(size_t)(k0 + brow) * 512 + n0 + bcol];
        __syncthreads();

#pragma unroll
        for (int k = 0; k < 16; ++k) {
            float4 a = *(const float4*)&As[k][ty * 4];
            float4 b = *(const float4*)&Bs[k][tx * 4];
            float ar[4] = {a.x, a.y, a.z, a.w};
            float br[4] = {b.x, b.y, b.z, b.w};
#pragma unroll
            for (int i = 0; i < 4; ++i)
#pragma unroll
                for (int j = 0; j < 4; ++j)
                    acc[i][j] = fmaf(ar[i], br[j], acc[i][j]);
        }
        __syncthreads();
    }

#pragma unroll
    for (int i = 0; i < 4; ++i) {
        int m = m0 + ty * 4 + i;
        int b = m / SS, s = m % SS;
#pragma unroll
        for (int j = 0; j < 4; ++j) {
            int c = n0 + tx * 4 + j;
            float v = acc[i][j] + bias[c];
            int h = c / DH, dd = c % DH;
            size_t idx = (((size_t)b * HH + h) * SS + s) * DH + dd;
            bf hi = __float2bfloat16_rn(v);
            bf lo = __float2bfloat16_rn(v - __bfloat162float(hi));
            ohi[idx] = hi;
            olo[idx] = lo;
        }
    }
}

// ---------------------------------------------------------------------------
// Plain fp32 projection (for O-proj).
// ---------------------------------------------------------------------------
__global__ __launch_bounds__(256) void proj_gemm_f32(
    const float* __restrict__ A, const float* __restrict__ W,
    const float* __restrict__ bias, float* __restrict__ out)
{
    __shared__ float As[16][68];
    __shared__ float Bs[16][68];

    const int tid = threadIdx.x;
    const int tx = tid & 15, ty = tid >> 4;
    const int n0 = blockIdx.x * 64;
    const int m0 = blockIdx.y * 64;

    const int arow = tid >> 2;
    const int ak4  = (tid & 3) * 4;
    const int brow = tid >> 4;
    const int bcol = (tid & 15) * 4;

    float acc[4][4] = {};

    for (int k0 = 0; k0 < 512; k0 += 16) {
        float4 av = *(const float4*)&A[(size_t)(m0 + arow) * 512 + k0 + ak4];
        As[ak4 + 0][arow] = av.x;
        As[ak4 + 1][arow] = av.y;
        As[ak4 + 2][arow] = av.z;
        As[ak4 + 3][arow] = av.w;
        *(float4*)&Bs[brow][bcol] =
            *(const float4*)&W[(size_t)(k0 + brow) * 512 + n0 + bcol];
        __syncthreads();

#pragma unroll
        for (int k = 0; k < 16; ++k) {
            float4 a = *(const float4*)&As[k][ty * 4];
            float4 b = *(const float4*)&Bs[k][tx * 4];
            float ar[4] = {a.x, a.y, a.z, a.w};
            float br[4] = {b.x, b.y, b.z, b.w};
#pragma unroll
            for (int i = 0; i < 4; ++i)
#pragma unroll
                for (int j = 0; j < 4; ++j)
                    acc[i][j] = fmaf(ar[i], br[j], acc[i][j]);
        }
        __syncthreads();
    }

#pragma unroll
    for (int i = 0; i < 4; ++i) {
        int m = m0 + ty * 4 + i;
#pragma unroll
        for (int j = 0; j < 4; ++j) {
            int c = n0 + tx * 4 + j;
            out[(size_t)m * 512 + c] = acc[i][j] + bias[c];
        }
    }
}

// ---------------------------------------------------------------------------
// Tensor-core flash attention. 128 q x 128 kv per iter, 8 warps.
// Warp w: q-rows [16w, 16w+16). bf16x3 split MMAs, fp32 accum.
// ---------------------------------------------------------------------------
__global__ __launch_bounds__(256, 1) void attn_mma(
    const bf* __restrict__ qhi, const bf* __restrict__ qlo,
    const bf* __restrict__ khi, const bf* __restrict__ klo,
    const bf* __restrict__ vhi, const bf* __restrict__ vlo,
    const float* __restrict__ mask, float* __restrict__ out)
{
    extern __shared__ char smc[];
    bf* Khi  = (bf*)smc;                    // [128][KPITCH]
    bf* Klo  = Khi + 128 * KPITCH;
    bf* Vthi = Klo + 128 * KPITCH;          // [64][VPITCH] transposed (dim, kv)
    bf* Vtlo = Vthi + 64 * VPITCH;
    float* Ms = (float*)(Vtlo + 64 * VPITCH);  // [128]

    const int tid  = threadIdx.x;
    const int warp = tid >> 5;
    const int lane = tid & 31;
    const int g    = lane >> 2;     // 0..7
    const int tg   = lane & 3;      // 0..3
    const int q0   = blockIdx.x * TQ;
    const int h    = blockIdx.y;
    const int b    = blockIdx.z;

    const size_t base = ((size_t)b * HH + h) * SS * DH;
    const bf* qh = qhi + base;
    const bf* ql = qlo + base;
    const bf* kh = khi + base;
    const bf* kl = klo + base;
    const bf* vh = vhi + base;
    const bf* vl = vlo + base;

    // ---- Q fragments in registers (rows r0=q0+16w+g, r1=r0+8) ----
    unsigned qah[4][4], qal[4][4];
    {
        const int r0 = q0 + warp * 16 + g;
        const int r1 = r0 + 8;
#pragma unroll
        for (int kc = 0; kc < 4; ++kc) {
            int c = kc * 16 + 2 * tg;
            qah[kc][0] = *(const unsigned*)&qh[(size_t)r0 * DH + c];
            qah[kc][1] = *(const unsigned*)&qh[(size_t)r1 * DH + c];
            qah[kc][2] = *(const unsigned*)&qh[(size_t)r0 * DH + c + 8];
            qah[kc][3] = *(const unsigned*)&qh[(size_t)r1 * DH + c + 8];
            qal[kc][0] = *(const unsigned*)&ql[(size_t)r0 * DH + c];
            qal[kc][1] = *(const unsigned*)&ql[(size_t)r1 * DH + c];
            qal[kc][2] = *(const unsigned*)&ql[(size_t)r0 * DH + c + 8];
            qal[kc][3] = *(const unsigned*)&ql[(size_t)r1 * DH + c + 8];
        }
    }

    float oacc[8][4];
#pragma unroll
    for (int t = 0; t < 8; ++t)
#pragma unroll
        for (int i = 0; i < 4; ++i) oacc[t][i] = 0.f;
    float m_a = -1e30f, m_b = -1e30f, l_a = 0.f, l_b = 0.f;

    for (int kt = 0; kt < SS; kt += TK) {
        __syncthreads();
        // ---- stage K (row-major) and V (transposed) tiles ----
        {
            const int row   = tid >> 1;
            const int cbase = (tid & 1) * 32;
            const size_t gro = (size_t)(kt + row) * DH + cbase;
            // K: 32 elems per thread via uint4 (8 bf16 each), stride 8 elems
#pragma unroll
            for (int i = 0; i < 4; ++i) {
                *(uint4*)&Khi[row * KPITCH + cbase + 8 * i] =
                    *(const uint4*)&kh[gro + 8 * i];
                *(uint4*)&Klo[row * KPITCH + cbase + 8 * i] =
                    *(const uint4*)&kl[gro + 8 * i];
            }
            // V: transpose into Vt (uint2 = 4 bf16, stride 4 elems)
#pragma unroll
            for (int i = 0; i < 8; ++i) {
                int c = cbase + 4 * i;
                uint2 xh = *(const uint2*)&vh[gro + 4 * i];
                uint2 xl = *(const uint2*)&vl[gro + 4 * i];
                const bf* ph = (const bf*)&xh;
                const bf* pl = (const bf*)&xl;
#pragma unroll
                for (int j = 0; j < 4; ++j) {
                    Vthi[(c + j) * VPITCH + row] = ph[j];
                    Vtlo[(c + j) * VPITCH + row] = pl[j];
                }
            }
            if (tid < TK) Ms[tid] = mask[(size_t)b * SS + kt + tid];
        }
        __syncthreads();

        // ---- S = Q K^T (16 n-tiles of m16n8) ----
        float sacc[16][4];
#pragma unroll
        for (int t = 0; t < 16; ++t) {
#pragma unroll
            for (int i = 0; i < 4; ++i) sacc[t][i] = 0.f;
            const int krow = 8 * t + g;
#pragma unroll
            for (int kc = 0; kc < 4; ++kc) {
                int c0 = kc * 16 + 2 * tg;
                unsigned bh0 = *(const unsigned*)&Khi[krow * KPITCH + c0];
                unsigned bh1 = *(const unsigned*)&Khi[krow * KPITCH + c0 + 8];
                unsigned bl0 = *(const unsigned*)&Klo[krow * KPITCH + c0];
                unsigned bl1 = *(const unsigned*)&Klo[krow * KPITCH + c0 + 8];
                mma_bf16(sacc[t], qah[kc], bh0, bh1);
                mma_bf16(sacc[t], qah[kc], bl0, bl1);
                mma_bf16(sacc[t], qal[kc], bh0, bh1);
            }
        }

        // ---- mask + row max ----
        float mloc_a = -1e30f, mloc_b = -1e30f;
#pragma unroll
        for (int t = 0; t < 16; ++t) {
            float2 mv = *(const float2*)&Ms[8 * t + 2 * tg];
            float m0 = mv.x * -1e9f, m1 = mv.y * -1e9f;
            sacc[t][0] += m0; sacc[t][1] += m1;
            sacc[t][2] += m0; sacc[t][3] += m1;
            mloc_a = fmaxf(mloc_a, fmaxf(sacc[t][0], sacc[t][1]));
            mloc_b = fmaxf(mloc_b, fmaxf(sacc[t][2], sacc[t][3]));
        }
#pragma unroll
        for (int off = 1; off < 4; off <<= 1) {
            mloc_a = fmaxf(mloc_a, __shfl_xor_sync(0xffffffffu, mloc_a, off));
            mloc_b = fmaxf(mloc_b, __shfl_xor_sync(0xffffffffu, mloc_b, off));
        }
        float mn_a = fmaxf(m_a, mloc_a);
        float mn_b = fmaxf(m_b, mloc_b);
        float corr_a = fexp(m_a - mn_a);
        float corr_b = fexp(m_b - mn_b);
        m_a = mn_a; m_b = mn_b;

        // ---- exp + row sum ----
        float rs_a = 0.f, rs_b = 0.f;
#pragma unroll
        for (int t = 0; t < 16; ++t) {
            sacc[t][0] = fexp(sacc[t][0] - m_a);
            sacc[t][1] = fexp(sacc[t][1] - m_a);
            sacc[t][2] = fexp(sacc[t][2] - m_b);
            sacc[t][3] = fexp(sacc[t][3] - m_b);
            rs_a += sacc[t][0] + sacc[t][1];
            rs_b += sacc[t][2] + sacc[t][3];
        }
#pragma unroll
        for (int off = 1; off < 4; off <<= 1) {
            rs_a += __shfl_xor_sync(0xffffffffu, rs_a, off);
            rs_b += __shfl_xor_sync(0xffffffffu, rs_b, off);
        }
        l_a = l_a * corr_a + rs_a;
        l_b = l_b * corr_b + rs_b;
#pragma unroll
        for (int t = 0; t < 8; ++t) {
            oacc[t][0] *= corr_a; oacc[t][1] *= corr_a;
            oacc[t][2] *= corr_b; oacc[t][3] *= corr_b;
        }

        // ---- O += P V (8 k-chunks of 16, 8 n-tiles of m16n8) ----
#pragma unroll
        for (int kc = 0; kc < 8; ++kc) {
            unsigned pah[4], pal[4];
#pragma unroll
            for (int half = 0; half < 2; ++half) {
                const float* s4 = sacc[2 * kc + half];
                bf h0 = __float2bfloat16_rn(s4[0]);
                bf h1 = __float2bfloat16_rn(s4[1]);
                bf h2 = __float2bfloat16_rn(s4[2]);
                bf h3 = __float2bfloat16_rn(s4[3]);
                pah[2 * half + 0] = pack_bf2(h0, h1);
                pah[2 * half + 1] = pack_bf2(h2, h3);
                pal[2 * half + 0] = pack_bf2(
                    __float2bfloat16_rn(s4[0] - __bfloat162float(h0)),
                    __float2bfloat16_rn(s4[1] - __bfloat162float(h1)));
                pal[2 * half + 1] = pack_bf2(
                    __float2bfloat16_rn(s4[2] - __bfloat162float(h2)),
                    __float2bfloat16_rn(s4[3] - __bfloat162float(h3)));
            }
            const int col0 = kc * 16 + 2 * tg;
#pragma unroll
            for (int t = 0; t < 8; ++t) {
                const int vrow = 8 * t + g;
                unsigned bh0 = *(const unsigned*)&Vthi[vrow * VPITCH + col0];
                unsigned bh1 = *(const unsigned*)&Vthi[vrow * VPITCH + col0 + 8];
                unsigned bl0 = *(const unsigned*)&Vtlo[vrow * VPITCH + col0];
                unsigned bl1 = *(const unsigned*)&Vtlo[vrow * VPITCH + col0 + 8];
                mma_bf16(oacc[t], pah, bh0, bh1);
                mma_bf16(oacc[t], pah, bl0, bl1);
                mma_bf16(oacc[t], pal, bh0, bh1);
            }
        }
    }

    // ---- epilogue: normalize, write merged-head [B,S,D] fp32 ----
    {
        float inva = 1.0f / l_a, invb = 1.0f / l_b;
        const int r0 = q0 + warp * 16 + g;
        const int r1 = r0 + 8;
#pragma unroll
        for (int t = 0; t < 8; ++t) {
            int c = h * DH + 8 * t + 2 * tg;
            float2 va = {oacc[t][0] * inva, oacc[t][1] * inva};
            float2 vb = {oacc[t][2] * invb, oacc[t][3] * invb};
            *(float2*)&out[((size_t)b * SS + r0) * DD + c] = va;
            *(float2*)&out[((size_t)b * SS + r1) * DD + c] = vb;
        }
    }
}

// ---------------------------------------------------------------------------
extern "C" void kernel_launch(void* const* d_in, const int* in_sizes, int n_in,
                              void* d_out, int out_size)
{
    (void)in_sizes; (void)n_in; (void)out_size;
    const float* q    = (const float*)d_in[0];
    const float* k    = (const float*)d_in[1];
    const float* v    = (const float*)d_in[2];
    const float* mask = (const float*)d_in[3];
    const float* wq   = (const float*)d_in[4];
    const float* bq   = (const float*)d_in[5];
    const float* wk   = (const float*)d_in[6];
    const float* bk   = (const float*)d_in[7];
    const float* wv   = (const float*)d_in[8];
    const float* bv   = (const float*)d_in[9];
    const float* wo   = (const float*)d_in[10];
    const float* bo   = (const float*)d_in[11];
    float* out = (float*)d_out;

    bf *qhi, *qlo, *khi, *klo, *vhi, *vlo;
    float* attn;
    cudaGetSymbolAddress((void**)&qhi, g_qhi);
    cudaGetSymbolAddress((void**)&qlo, g_qlo);
    cudaGetSymbolAddress((void**)&khi, g_khi);
    cudaGetSymbolAddress((void**)&klo, g_klo);
    cudaGetSymbolAddress((void**)&vhi, g_vhi);
    cudaGetSymbolAddress((void**)&vlo, g_vlo);
    cudaGetSymbolAddress((void**)&attn, g_attn);

    const int ATTN_SMEM =
        (2 * 128 * KPITCH + 2 * 64 * VPITCH) * 2 + 128 * 4;  // 72192 B
    static int smem_set = 0;
    if (!smem_set) {
        cudaFuncSetAttribute(attn_mma,
                             cudaFuncAttributeMaxDynamicSharedMemorySize,
                             ATTN_SMEM);
        smem_set = 1;
    }

    dim3 gproj(DD / 64, M_ROWS / 64);  // (8, 128)
    proj_gemm_split<<<gproj, 256>>>(q, wq, bq, qhi, qlo);
    proj_gemm_split<<<gproj, 256>>>(k, wk, bk, khi, klo);
    proj_gemm_split<<<gproj, 256>>>(v, wv, bv, vhi, vlo);

    dim3 gattn(SS / TQ, HH, BB);       // (32, 8, 2)
    attn_mma<<<gattn, 256, ATTN_SMEM>>>(qhi, qlo, khi, klo, vhi, vlo,
                                        mask, attn);

    proj_gemm_f32<<<gproj, 256>>>(attn, wo, bo, out);
}

// round 7
// speedup vs baseline: 3.7453x; 1.0870x over previous
#include <cuda_runtime.h>
#include <cuda_bf16.h>
#include <math.h>

#define BB 2
#define SS 4096
#define DD 512
#define HH 8
#define DH 64
#define M_ROWS (BB*SS)   // 8192

#define TQ 128
#define TK 128
#define KPITCH 72        // K smem pitch in bf16 elems
#define VPITCH 136       // Vt smem pitch in bf16 elems

typedef __nv_bfloat16 bf;

// Scratch (allocation-free rule: __device__ globals). [B,H,S,d] layout.
__device__ bf g_qhi[(size_t)BB*HH*SS*DH];
__device__ bf g_qlo[(size_t)BB*HH*SS*DH];
__device__ bf g_khi[(size_t)BB*HH*SS*DH];
__device__ bf g_klo[(size_t)BB*HH*SS*DH];
__device__ bf g_vhi[(size_t)BB*HH*SS*DH];
__device__ bf g_vlo[(size_t)BB*HH*SS*DH];
__device__ float g_attn[(size_t)M_ROWS*DD];   // [B*S, D]

// ---------------------------------------------------------------------------
// fast exp on FMA/ALU pipes (no MUFU). Valid for softmax args (x <= 0-ish).
// ---------------------------------------------------------------------------
__device__ __forceinline__ float fexp(float x)
{
    float y  = fmaxf(x, -80.0f) * 1.44269504f;     // log2(e)
    float yn = y + 12582912.0f;                    // 1.5*2^23 round-to-int
    float nf = yn - 12582912.0f;
    float f  = y - nf;                             // f in [-0.5, 0.5]
    int   sc = (__float_as_int(yn) - 0x4B400000 + 127) << 23;  // 2^n bits
    float p  = 1.3333558e-3f;
    p = fmaf(p, f, 9.6181291e-3f);
    p = fmaf(p, f, 5.5504109e-2f);
    p = fmaf(p, f, 2.4022651e-1f);
    p = fmaf(p, f, 6.9314718e-1f);
    p = fmaf(p, f, 1.0f);
    return __int_as_float(sc) * p;
}

__device__ __forceinline__ void mma_bf16(float* c, const unsigned* a,
                                         unsigned b0, unsigned b1)
{
    asm("mma.sync.aligned.m16n8k16.row.col.f32.bf16.bf16.f32 "
        "{%0,%1,%2,%3},{%4,%5,%6,%7},{%8,%9},{%0,%1,%2,%3};"
        : "+f"(c[0]), "+f"(c[1]), "+f"(c[2]), "+f"(c[3])
        : "r"(a[0]), "r"(a[1]), "r"(a[2]), "r"(a[3]), "r"(b0), "r"(b1));
}

__device__ __forceinline__ unsigned pack_bf2(bf a, bf b)
{
    __nv_bfloat162 t = __halves2bfloat162(a, b);   // a -> low, b -> high
    return *(unsigned*)&t;
}

__device__ __forceinline__ void split2(float x, float y,
                                       unsigned& hi, unsigned& lo)
{
    bf hx = __float2bfloat16_rn(x), hy = __float2bfloat16_rn(y);
    hi = pack_bf2(hx, hy);
    lo = pack_bf2(__float2bfloat16_rn(x - __bfloat162float(hx)),
                  __float2bfloat16_rn(y - __bfloat162float(hy)));
}

// ---------------------------------------------------------------------------
// Tensor-core projection GEMM: out = A[8192 x 512] @ W[512 x 512] + bias.
// CTA = 128x128, BK=16 double-buffered. 8 warps, warp w: m-rows [16w,16w+16).
// Split-bf16 3-term MMAs (same fragment scheme as attn_mma, proven correct).
// MODE 0: scatter hi/lo bf16 into [B,H,S,d].  MODE 1: fp32 row-major.
// ---------------------------------------------------------------------------
template<int MODE>
__global__ __launch_bounds__(256, 2) void proj_mma(
    const float* __restrict__ A, const float* __restrict__ W,
    const float* __restrict__ bias,
    bf* __restrict__ ohi, bf* __restrict__ olo, float* __restrict__ of32)
{
    __shared__ bf Ah[2][128*16], Al[2][128*16];
    __shared__ bf Wh[2][128*16], Wl[2][128*16];

    const int tid  = threadIdx.x;
    const int warp = tid >> 5, lane = tid & 31;
    const int g = lane >> 2, tg = lane & 3;
    const int n0 = blockIdx.x * 128;
    const int m0 = blockIdx.y * 128;

    // staging indices
    const int sm  = tid >> 1;            // A: row 0..127
    const int skk = (tid & 1) * 8;       // A: k offset 0/8
    const int wkk = tid & 15;            // W: k 0..15
    const int wn8 = (tid >> 4) * 8;      // W: n offset 0..120

    float acc[16][4];
#pragma unroll
    for (int t = 0; t < 16; ++t)
#pragma unroll
        for (int i = 0; i < 4; ++i) acc[t][i] = 0.f;

    // ---- stage chunk 0 into buffer 0 ----
    {
        const float* Ap = A + (size_t)(m0 + sm) * 512 + skk;
        float4 u1 = *(const float4*)Ap;
        float4 u2 = *(const float4*)(Ap + 4);
        unsigned h0, l0, h1, l1, h2, l2, h3, l3;
        split2(u1.x, u1.y, h0, l0); split2(u1.z, u1.w, h1, l1);
        split2(u2.x, u2.y, h2, l2); split2(u2.z, u2.w, h3, l3);
        *(uint4*)&Ah[0][sm * 16 + skk] = make_uint4(h0, h1, h2, h3);
        *(uint4*)&Al[0][sm * 16 + skk] = make_uint4(l0, l1, l2, l3);

        const float* Wp = W + (size_t)wkk * 512 + n0 + wn8;
        float4 w1 = *(const float4*)Wp;
        float4 w2 = *(const float4*)(Wp + 4);
        float wv[8] = {w1.x, w1.y, w1.z, w1.w, w2.x, w2.y, w2.z, w2.w};
#pragma unroll
        for (int j = 0; j < 8; ++j) {
            bf h = __float2bfloat16_rn(wv[j]);
            Wh[0][(wn8 + j) * 16 + wkk] = h;
            Wl[0][(wn8 + j) * 16 + wkk] =
                __float2bfloat16_rn(wv[j] - __bfloat162float(h));
        }
    }
    __syncthreads();

#pragma unroll 1
    for (int c = 0; c < 32; ++c) {
        const int cur = c & 1;
        // ---- prefetch chunk c+1 into the other buffer ----
        if (c + 1 < 32) {
            const int nxt = (c + 1) & 1;
            const int k0 = (c + 1) * 16;
            const float* Ap = A + (size_t)(m0 + sm) * 512 + k0 + skk;
            float4 u1 = *(const float4*)Ap;
            float4 u2 = *(const float4*)(Ap + 4);
            unsigned h0, l0, h1, l1, h2, l2, h3, l3;
            split2(u1.x, u1.y, h0, l0); split2(u1.z, u1.w, h1, l1);
            split2(u2.x, u2.y, h2, l2); split2(u2.z, u2.w, h3, l3);
            *(uint4*)&Ah[nxt][sm * 16 + skk] = make_uint4(h0, h1, h2, h3);
            *(uint4*)&Al[nxt][sm * 16 + skk] = make_uint4(l0, l1, l2, l3);

            const float* Wp = W + (size_t)(k0 + wkk) * 512 + n0 + wn8;
            float4 w1 = *(const float4*)Wp;
            float4 w2 = *(const float4*)(Wp + 4);
            float wv[8] = {w1.x, w1.y, w1.z, w1.w, w2.x, w2.y, w2.z, w2.w};
#pragma unroll
            for (int j = 0; j < 8; ++j) {
                bf h = __float2bfloat16_rn(wv[j]);
                Wh[nxt][(wn8 + j) * 16 + wkk] = h;
                Wl[nxt][(wn8 + j) * 16 + wkk] =
                    __float2bfloat16_rn(wv[j] - __bfloat162float(h));
            }
        }

        // ---- compute on buffer cur ----
        {
            const int arow = warp * 16 + g;
            unsigned ah[4], al[4];
            ah[0] = *(const unsigned*)&Ah[cur][arow * 16 + 2 * tg];
            ah[1] = *(const unsigned*)&Ah[cur][(arow + 8) * 16 + 2 * tg];
            ah[2] = *(const unsigned*)&Ah[cur][arow * 16 + 2 * tg + 8];
            ah[3] = *(const unsigned*)&Ah[cur][(arow + 8) * 16 + 2 * tg + 8];
            al[0] = *(const unsigned*)&Al[cur][arow * 16 + 2 * tg];
            al[1] = *(const unsigned*)&Al[cur][(arow + 8) * 16 + 2 * tg];
            al[2] = *(const unsigned*)&Al[cur][arow * 16 + 2 * tg + 8];
            al[3] = *(const unsigned*)&Al[cur][(arow + 8) * 16 + 2 * tg + 8];
#pragma unroll
            for (int t = 0; t < 16; ++t) {
                const int n = 8 * t + g;
                unsigned bh0 = *(const unsigned*)&Wh[cur][n * 16 + 2 * tg];
                unsigned bh1 = *(const unsigned*)&Wh[cur][n * 16 + 2 * tg + 8];
                unsigned bl0 = *(const unsigned*)&Wl[cur][n * 16 + 2 * tg];
                unsigned bl1 = *(const unsigned*)&Wl[cur][n * 16 + 2 * tg + 8];
                mma_bf16(acc[t], ah, bh0, bh1);
                mma_bf16(acc[t], ah, bl0, bl1);
                mma_bf16(acc[t], al, bh0, bh1);
            }
        }
        __syncthreads();
    }

    // ---- epilogue ----
    const int r0 = m0 + warp * 16 + g;
    const int r1 = r0 + 8;
#pragma unroll
    for (int t = 0; t < 16; ++t) {
        const int n = n0 + 8 * t + 2 * tg;
        float2 bv = *(const float2*)&bias[n];
        float v00 = acc[t][0] + bv.x, v01 = acc[t][1] + bv.y;  // row r0
        float v10 = acc[t][2] + bv.x, v11 = acc[t][3] + bv.y;  // row r1
        if (MODE == 0) {
            const int h = n >> 6, dd = n & 63;
            unsigned hi0, lo0, hi1, lo1;
            split2(v00, v01, hi0, lo0);
            split2(v10, v11, hi1, lo1);
            {
                int b = r0 >> 12, s = r0 & 4095;
                size_t i0 = (((size_t)b * HH + h) * SS + s) * DH + dd;
                *(unsigned*)&ohi[i0] = hi0;
                *(unsigned*)&olo[i0] = lo0;
            }
            {
                int b = r1 >> 12, s = r1 & 4095;
                size_t i1 = (((size_t)b * HH + h) * SS + s) * DH + dd;
                *(unsigned*)&ohi[i1] = hi1;
                *(unsigned*)&olo[i1] = lo1;
            }
        } else {
            *(float2*)&of32[(size_t)r0 * 512 + n] = make_float2(v00, v01);
            *(float2*)&of32[(size_t)r1 * 512 + n] = make_float2(v10, v11);
        }
    }
}

// ---------------------------------------------------------------------------
// Tensor-core flash attention. 128 q x 128 kv per iter, 8 warps.
// Warp w: q-rows [16w, 16w+16). bf16x3 split MMAs, fp32 accum. (unchanged)
// ---------------------------------------------------------------------------
__global__ __launch_bounds__(256, 1) void attn_mma(
    const bf* __restrict__ qhi, const bf* __restrict__ qlo,
    const bf* __restrict__ khi, const bf* __restrict__ klo,
    const bf* __restrict__ vhi, const bf* __restrict__ vlo,
    const float* __restrict__ mask, float* __restrict__ out)
{
    extern __shared__ char smc[];
    bf* Khi  = (bf*)smc;                    // [128][KPITCH]
    bf* Klo  = Khi + 128 * KPITCH;
    bf* Vthi = Klo + 128 * KPITCH;          // [64][VPITCH] transposed (dim, kv)
    bf* Vtlo = Vthi + 64 * VPITCH;
    float* Ms = (float*)(Vtlo + 64 * VPITCH);  // [128]

    const int tid  = threadIdx.x;
    const int warp = tid >> 5;
    const int lane = tid & 31;
    const int g    = lane >> 2;     // 0..7
    const int tg   = lane & 3;      // 0..3
    const int q0   = blockIdx.x * TQ;
    const int h    = blockIdx.y;
    const int b    = blockIdx.z;

    const size_t base = ((size_t)b * HH + h) * SS * DH;
    const bf* qh = qhi + base;
    const bf* ql = qlo + base;
    const bf* kh = khi + base;
    const bf* kl = klo + base;
    const bf* vh = vhi + base;
    const bf* vl = vlo + base;

    // ---- Q fragments in registers (rows r0=q0+16w+g, r1=r0+8) ----
    unsigned qah[4][4], qal[4][4];
    {
        const int r0 = q0 + warp * 16 + g;
        const int r1 = r0 + 8;
#pragma unroll
        for (int kc = 0; kc < 4; ++kc) {
            int c = kc * 16 + 2 * tg;
            qah[kc][0] = *(const unsigned*)&qh[(size_t)r0 * DH + c];
            qah[kc][1] = *(const unsigned*)&qh[(size_t)r1 * DH + c];
            qah[kc][2] = *(const unsigned*)&qh[(size_t)r0 * DH + c + 8];
            qah[kc][3] = *(const unsigned*)&qh[(size_t)r1 * DH + c + 8];
            qal[kc][0] = *(const unsigned*)&ql[(size_t)r0 * DH + c];
            qal[kc][1] = *(const unsigned*)&ql[(size_t)r1 * DH + c];
            qal[kc][2] = *(const unsigned*)&ql[(size_t)r0 * DH + c + 8];
            qal[kc][3] = *(const unsigned*)&ql[(size_t)r1 * DH + c + 8];
        }
    }

    float oacc[8][4];
#pragma unroll
    for (int t = 0; t < 8; ++t)
#pragma unroll
        for (int i = 0; i < 4; ++i) oacc[t][i] = 0.f;
    float m_a = -1e30f, m_b = -1e30f, l_a = 0.f, l_b = 0.f;

    for (int kt = 0; kt < SS; kt += TK) {
        __syncthreads();
        // ---- stage K (row-major) and V (transposed) tiles ----
        {
            const int row   = tid >> 1;
            const int cbase = (tid & 1) * 32;
            const size_t gro = (size_t)(kt + row) * DH + cbase;
#pragma unroll
            for (int i = 0; i < 4; ++i) {
                *(uint4*)&Khi[row * KPITCH + cbase + 8 * i] =
                    *(const uint4*)&kh[gro + 8 * i];
                *(uint4*)&Klo[row * KPITCH + cbase + 8 * i] =
                    *(const uint4*)&kl[gro + 8 * i];
            }
#pragma unroll
            for (int i = 0; i < 8; ++i) {
                int c = cbase + 4 * i;
                uint2 xh = *(const uint2*)&vh[gro + 4 * i];
                uint2 xl = *(const uint2*)&vl[gro + 4 * i];
                const bf* ph = (const bf*)&xh;
                const bf* pl = (const bf*)&xl;
#pragma unroll
                for (int j = 0; j < 4; ++j) {
                    Vthi[(c + j) * VPITCH + row] = ph[j];
                    Vtlo[(c + j) * VPITCH + row] = pl[j];
                }
            }
            if (tid < TK) Ms[tid] = mask[(size_t)b * SS + kt + tid];
        }
        __syncthreads();

        // ---- S = Q K^T (16 n-tiles of m16n8) ----
        float sacc[16][4];
#pragma unroll
        for (int t = 0; t < 16; ++t) {
#pragma unroll
            for (int i = 0; i < 4; ++i) sacc[t][i] = 0.f;
            const int krow = 8 * t + g;
#pragma unroll
            for (int kc = 0; kc < 4; ++kc) {
                int c0 = kc * 16 + 2 * tg;
                unsigned bh0 = *(const unsigned*)&Khi[krow * KPITCH + c0];
                unsigned bh1 = *(const unsigned*)&Khi[krow * KPITCH + c0 + 8];
                unsigned bl0 = *(const unsigned*)&Klo[krow * KPITCH + c0];
                unsigned bl1 = *(const unsigned*)&Klo[krow * KPITCH + c0 + 8];
                mma_bf16(sacc[t], qah[kc], bh0, bh1);
                mma_bf16(sacc[t], qah[kc], bl0, bl1);
                mma_bf16(sacc[t], qal[kc], bh0, bh1);
            }
        }

        // ---- mask + row max ----
        float mloc_a = -1e30f, mloc_b = -1e30f;
#pragma unroll
        for (int t = 0; t < 16; ++t) {
            float2 mv = *(const float2*)&Ms[8 * t + 2 * tg];
            float m0 = mv.x * -1e9f, m1 = mv.y * -1e9f;
            sacc[t][0] += m0; sacc[t][1] += m1;
            sacc[t][2] += m0; sacc[t][3] += m1;
            mloc_a = fmaxf(mloc_a, fmaxf(sacc[t][0], sacc[t][1]));
            mloc_b = fmaxf(mloc_b, fmaxf(sacc[t][2], sacc[t][3]));
        }
#pragma unroll
        for (int off = 1; off < 4; off <<= 1) {
            mloc_a = fmaxf(mloc_a, __shfl_xor_sync(0xffffffffu, mloc_a, off));
            mloc_b = fmaxf(mloc_b, __shfl_xor_sync(0xffffffffu, mloc_b, off));
        }
        float mn_a = fmaxf(m_a, mloc_a);
        float mn_b = fmaxf(m_b, mloc_b);
        float corr_a = fexp(m_a - mn_a);
        float corr_b = fexp(m_b - mn_b);
        m_a = mn_a; m_b = mn_b;

        // ---- exp + row sum ----
        float rs_a = 0.f, rs_b = 0.f;
#pragma unroll
        for (int t = 0; t < 16; ++t) {
            sacc[t][0] = fexp(sacc[t][0] - m_a);
            sacc[t][1] = fexp(sacc[t][1] - m_a);
            sacc[t][2] = fexp(sacc[t][2] - m_b);
            sacc[t][3] = fexp(sacc[t][3] - m_b);
            rs_a += sacc[t][0] + sacc[t][1];
            rs_b += sacc[t][2] + sacc[t][3];
        }
#pragma unroll
        for (int off = 1; off < 4; off <<= 1) {
            rs_a += __shfl_xor_sync(0xffffffffu, rs_a, off);
            rs_b += __shfl_xor_sync(0xffffffffu, rs_b, off);
        }
        l_a = l_a * corr_a + rs_a;
        l_b = l_b * corr_b + rs_b;
#pragma unroll
        for (int t = 0; t < 8; ++t) {
            oacc[t][0] *= corr_a; oacc[t][1] *= corr_a;
            oacc[t][2] *= corr_b; oacc[t][3] *= corr_b;
        }

        // ---- O += P V (8 k-chunks of 16, 8 n-tiles of m16n8) ----
#pragma unroll
        for (int kc = 0; kc < 8; ++kc) {
            unsigned pah[4], pal[4];
#pragma unroll
            for (int half = 0; half < 2; ++half) {
                const float* s4 = sacc[2 * kc + half];
                bf h0 = __float2bfloat16_rn(s4[0]);
                bf h1 = __float2bfloat16_rn(s4[1]);
                bf h2 = __float2bfloat16_rn(s4[2]);
                bf h3 = __float2bfloat16_rn(s4[3]);
                pah[2 * half + 0] = pack_bf2(h0, h1);
                pah[2 * half + 1] = pack_bf2(h2, h3);
                pal[2 * half + 0] = pack_bf2(
                    __float2bfloat16_rn(s4[0] - __bfloat162float(h0)),
                    __float2bfloat16_rn(s4[1] - __bfloat162float(h1)));
                pal[2 * half + 1] = pack_bf2(
                    __float2bfloat16_rn(s4[2] - __bfloat162float(h2)),
                    __float2bfloat16_rn(s4[3] - __bfloat162float(h3)));
            }
            const int col0 = kc * 16 + 2 * tg;
#pragma unroll
            for (int t = 0; t < 8; ++t) {
                const int vrow = 8 * t + g;
                unsigned bh0 = *(const unsigned*)&Vthi[vrow * VPITCH + col0];
                unsigned bh1 = *(const unsigned*)&Vthi[vrow * VPITCH + col0 + 8];
                unsigned bl0 = *(const unsigned*)&Vtlo[vrow * VPITCH + col0];
                unsigned bl1 = *(const unsigned*)&Vtlo[vrow * VPITCH + col0 + 8];
                mma_bf16(oacc[t], pah, bh0, bh1);
                mma_bf16(oacc[t], pah, bl0, bl1);
                mma_bf16(oacc[t], pal, bh0, bh1);
            }
        }
    }

    // ---- epilogue: normalize, write merged-head [B,S,D] fp32 ----
    {
        float inva = 1.0f / l_a, invb = 1.0f / l_b;
        const int r0 = q0 + warp * 16 + g;
        const int r1 = r0 + 8;
#pragma unroll
        for (int t = 0; t < 8; ++t) {
            int c = h * DH + 8 * t + 2 * tg;
            float2 va = {oacc[t][0] * inva, oacc[t][1] * inva};
            float2 vb = {oacc[t][2] * invb, oacc[t][3] * invb};
            *(float2*)&out[((size_t)b * SS + r0) * DD + c] = va;
            *(float2*)&out[((size_t)b * SS + r1) * DD + c] = vb;
        }
    }
}

// ---------------------------------------------------------------------------
extern "C" void kernel_launch(void* const* d_in, const int* in_sizes, int n_in,
                              void* d_out, int out_size)
{
    (void)in_sizes; (void)n_in; (void)out_size;
    const float* q    = (const float*)d_in[0];
    const float* k    = (const float*)d_in[1];
    const float* v    = (const float*)d_in[2];
    const float* mask = (const float*)d_in[3];
    const float* wq   = (const float*)d_in[4];
    const float* bq   = (const float*)d_in[5];
    const float* wk   = (const float*)d_in[6];
    const float* bk   = (const float*)d_in[7];
    const float* wv   = (const float*)d_in[8];
    const float* bv   = (const float*)d_in[9];
    const float* wo   = (const float*)d_in[10];
    const float* bo   = (const float*)d_in[11];
    float* out = (float*)d_out;

    bf *qhi, *qlo, *khi, *klo, *vhi, *vlo;
    float* attn;
    cudaGetSymbolAddress((void**)&qhi, g_qhi);
    cudaGetSymbolAddress((void**)&qlo, g_qlo);
    cudaGetSymbolAddress((void**)&khi, g_khi);
    cudaGetSymbolAddress((void**)&klo, g_klo);
    cudaGetSymbolAddress((void**)&vhi, g_vhi);
    cudaGetSymbolAddress((void**)&vlo, g_vlo);
    cudaGetSymbolAddress((void**)&attn, g_attn);

    const int ATTN_SMEM =
        (2 * 128 * KPITCH + 2 * 64 * VPITCH) * 2 + 128 * 4;  // 72192 B
    static int smem_set = 0;
    if (!smem_set) {
        cudaFuncSetAttribute(attn_mma,
                             cudaFuncAttributeMaxDynamicSharedMemorySize,
                             ATTN_SMEM);
        smem_set = 1;
    }

    dim3 gproj(DD / 128, M_ROWS / 128);  // (4, 64)
    proj_mma<0><<<gproj, 256>>>(q, wq, bq, qhi, qlo, nullptr);
    proj_mma<0><<<gproj, 256>>>(k, wk, bk, khi, klo, nullptr);
    proj_mma<0><<<gproj, 256>>>(v, wv, bv, vhi, vlo, nullptr);

    dim3 gattn(SS / TQ, HH, BB);       // (32, 8, 2)
    attn_mma<<<gattn, 256, ATTN_SMEM>>>(qhi, qlo, khi, klo, vhi, vlo,
                                        mask, attn);

    proj_mma<1><<<gproj, 256>>>(attn, wo, bo, nullptr, nullptr, out);
}

// round 9
// speedup vs baseline: 4.4607x; 1.1910x over previous
#include <cuda_runtime.h>
#include <cuda_bf16.h>
#include <math.h>

#define BB 2
#define SS 4096
#define DD 512
#define HH 8
#define DH 64
#define M_ROWS (BB*SS)   // 8192

#define TQ 128
#define TK 128
#define KPITCH 72        // K/V smem pitch in bf16 elems (stride 4 banks mod 32)

typedef __nv_bfloat16 bf;

// Scratch (allocation-free rule: __device__ globals). [B,H,S,d] layout.
__device__ bf g_qhi[(size_t)BB*HH*SS*DH];
__device__ bf g_qlo[(size_t)BB*HH*SS*DH];
__device__ bf g_khi[(size_t)BB*HH*SS*DH];
__device__ bf g_klo[(size_t)BB*HH*SS*DH];
__device__ bf g_vhi[(size_t)BB*HH*SS*DH];
__device__ bf g_vlo[(size_t)BB*HH*SS*DH];
__device__ float g_attn[(size_t)M_ROWS*DD];   // [B*S, D]

__device__ __forceinline__ void mma_bf16(float* c, const unsigned* a,
                                         unsigned b0, unsigned b1)
{
    asm("mma.sync.aligned.m16n8k16.row.col.f32.bf16.bf16.f32 "
        "{%0,%1,%2,%3},{%4,%5,%6,%7},{%8,%9},{%0,%1,%2,%3};"
        : "+f"(c[0]), "+f"(c[1]), "+f"(c[2]), "+f"(c[3])
        : "r"(a[0]), "r"(a[1]), "r"(a[2]), "r"(a[3]), "r"(b0), "r"(b1));
}

__device__ __forceinline__ unsigned pack_bf2(bf a, bf b)
{
    __nv_bfloat162 t = __halves2bfloat162(a, b);   // a -> low, b -> high
    return *(unsigned*)&t;
}

__device__ __forceinline__ void split2(float x, float y,
                                       unsigned& hi, unsigned& lo)
{
    bf hx = __float2bfloat16_rn(x), hy = __float2bfloat16_rn(y);
    hi = pack_bf2(hx, hy);
    lo = pack_bf2(__float2bfloat16_rn(x - __bfloat162float(hx)),
                  __float2bfloat16_rn(y - __bfloat162float(hy)));
}

__device__ __forceinline__ unsigned sm_u32(const void* p)
{
    return (unsigned)__cvta_generic_to_shared(p);
}

__device__ __forceinline__ void ldsm_x4(unsigned addr, unsigned& r0,
                                        unsigned& r1, unsigned& r2, unsigned& r3)
{
    asm volatile("ldmatrix.sync.aligned.m8n8.x4.shared.b16 {%0,%1,%2,%3},[%4];"
                 : "=r"(r0), "=r"(r1), "=r"(r2), "=r"(r3) : "r"(addr));
}

__device__ __forceinline__ void ldsm_x4_t(unsigned addr, unsigned& r0,
                                          unsigned& r1, unsigned& r2, unsigned& r3)
{
    asm volatile("ldmatrix.sync.aligned.m8n8.x4.trans.shared.b16 {%0,%1,%2,%3},[%4];"
                 : "=r"(r0), "=r"(r1), "=r"(r2), "=r"(r3) : "r"(addr));
}

// ---------------------------------------------------------------------------
// Tensor-core projection GEMM: out = A[8192 x 512] @ W[512 x 512] + bias.
// CTA = 128x128, BK=16 double-buffered. 8 warps, warp w: m-rows [16w,16w+16).
// MODE 0: scatter hi/lo bf16 into [B,H,S,d].  MODE 1: fp32 row-major.
// ---------------------------------------------------------------------------
template<int MODE>
__global__ __launch_bounds__(256, 2) void proj_mma(
    const float* __restrict__ A, const float* __restrict__ W,
    const float* __restrict__ bias,
    bf* __restrict__ ohi, bf* __restrict__ olo, float* __restrict__ of32)
{
    __shared__ bf Ah[2][128*16], Al[2][128*16];
    __shared__ bf Wh[2][128*16], Wl[2][128*16];

    const int tid  = threadIdx.x;
    const int warp = tid >> 5, lane = tid & 31;
    const int g = lane >> 2, tg = lane & 3;
    const int n0 = blockIdx.x * 128;
    const int m0 = blockIdx.y * 128;

    const int sm  = tid >> 1;            // A: row 0..127
    const int skk = (tid & 1) * 8;       // A: k offset 0/8
    const int wkk = tid & 15;            // W: k 0..15
    const int wn8 = (tid >> 4) * 8;      // W: n offset 0..120

    float acc[16][4];
#pragma unroll
    for (int t = 0; t < 16; ++t)
#pragma unroll
        for (int i = 0; i < 4; ++i) acc[t][i] = 0.f;

    // ---- stage chunk 0 into buffer 0 ----
    {
        const float* Ap = A + (size_t)(m0 + sm) * 512 + skk;
        float4 u1 = *(const float4*)Ap;
        float4 u2 = *(const float4*)(Ap + 4);
        unsigned h0, l0, h1, l1, h2, l2, h3, l3;
        split2(u1.x, u1.y, h0, l0); split2(u1.z, u1.w, h1, l1);
        split2(u2.x, u2.y, h2, l2); split2(u2.z, u2.w, h3, l3);
        *(uint4*)&Ah[0][sm * 16 + skk] = make_uint4(h0, h1, h2, h3);
        *(uint4*)&Al[0][sm * 16 + skk] = make_uint4(l0, l1, l2, l3);

        const float* Wp = W + (size_t)wkk * 512 + n0 + wn8;
        float4 w1 = *(const float4*)Wp;
        float4 w2 = *(const float4*)(Wp + 4);
        float wv[8] = {w1.x, w1.y, w1.z, w1.w, w2.x, w2.y, w2.z, w2.w};
#pragma unroll
        for (int j = 0; j < 8; ++j) {
            bf h = __float2bfloat16_rn(wv[j]);
            Wh[0][(wn8 + j) * 16 + wkk] = h;
            Wl[0][(wn8 + j) * 16 + wkk] =
                __float2bfloat16_rn(wv[j] - __bfloat162float(h));
        }
    }
    __syncthreads();

#pragma unroll 1
    for (int c = 0; c < 32; ++c) {
        const int cur = c & 1;
        if (c + 1 < 32) {
            const int nxt = (c + 1) & 1;
            const int k0 = (c + 1) * 16;
            const float* Ap = A + (size_t)(m0 + sm) * 512 + k0 + skk;
            float4 u1 = *(const float4*)Ap;
            float4 u2 = *(const float4*)(Ap + 4);
            unsigned h0, l0, h1, l1, h2, l2, h3, l3;
            split2(u1.x, u1.y, h0, l0); split2(u1.z, u1.w, h1, l1);
            split2(u2.x, u2.y, h2, l2); split2(u2.z, u2.w, h3, l3);
            *(uint4*)&Ah[nxt][sm * 16 + skk] = make_uint4(h0, h1, h2, h3);
            *(uint4*)&Al[nxt][sm * 16 + skk] = make_uint4(l0, l1, l2, l3);

            const float* Wp = W + (size_t)(k0 + wkk) * 512 + n0 + wn8;
            float4 w1 = *(const float4*)Wp;
            float4 w2 = *(const float4*)(Wp + 4);
            float wv[8] = {w1.x, w1.y, w1.z, w1.w, w2.x, w2.y, w2.z, w2.w};
#pragma unroll
            for (int j = 0; j < 8; ++j) {
                bf h = __float2bfloat16_rn(wv[j]);
                Wh[nxt][(wn8 + j) * 16 + wkk] = h;
                Wl[nxt][(wn8 + j) * 16 + wkk] =
                    __float2bfloat16_rn(wv[j] - __bfloat162float(h));
            }
        }

        {
            const int arow = warp * 16 + g;
            unsigned ah[4], al[4];
            ah[0] = *(const unsigned*)&Ah[cur][arow * 16 + 2 * tg];
            ah[1] = *(const unsigned*)&Ah[cur][(arow + 8) * 16 + 2 * tg];
            ah[2] = *(const unsigned*)&Ah[cur][arow * 16 + 2 * tg + 8];
            ah[3] = *(const unsigned*)&Ah[cur][(arow + 8) * 16 + 2 * tg + 8];
            al[0] = *(const unsigned*)&Al[cur][arow * 16 + 2 * tg];
            al[1] = *(const unsigned*)&Al[cur][(arow + 8) * 16 + 2 * tg];
            al[2] = *(const unsigned*)&Al[cur][arow * 16 + 2 * tg + 8];
            al[3] = *(const unsigned*)&Al[cur][(arow + 8) * 16 + 2 * tg + 8];
#pragma unroll
            for (int t = 0; t < 16; ++t) {
                const int n = 8 * t + g;
                unsigned bh0 = *(const unsigned*)&Wh[cur][n * 16 + 2 * tg];
                unsigned bh1 = *(const unsigned*)&Wh[cur][n * 16 + 2 * tg + 8];
                unsigned bl0 = *(const unsigned*)&Wl[cur][n * 16 + 2 * tg];
                unsigned bl1 = *(const unsigned*)&Wl[cur][n * 16 + 2 * tg + 8];
                mma_bf16(acc[t], ah, bh0, bh1);
                mma_bf16(acc[t], ah, bl0, bl1);
                mma_bf16(acc[t], al, bh0, bh1);
            }
        }
        __syncthreads();
    }

    // ---- epilogue ----
    const int r0 = m0 + warp * 16 + g;
    const int r1 = r0 + 8;
#pragma unroll
    for (int t = 0; t < 16; ++t) {
        const int n = n0 + 8 * t + 2 * tg;
        float2 bv = *(const float2*)&bias[n];
        float v00 = acc[t][0] + bv.x, v01 = acc[t][1] + bv.y;  // row r0
        float v10 = acc[t][2] + bv.x, v11 = acc[t][3] + bv.y;  // row r1
        if (MODE == 0) {
            const int h = n >> 6, dd = n & 63;
            unsigned hi0, lo0, hi1, lo1;
            split2(v00, v01, hi0, lo0);
            split2(v10, v11, hi1, lo1);
            {
                int b = r0 >> 12, s = r0 & 4095;
                size_t i0 = (((size_t)b * HH + h) * SS + s) * DH + dd;
                *(unsigned*)&ohi[i0] = hi0;
                *(unsigned*)&olo[i0] = lo0;
            }
            {
                int b = r1 >> 12, s = r1 & 4095;
                size_t i1 = (((size_t)b * HH + h) * SS + s) * DH + dd;
                *(unsigned*)&ohi[i1] = hi1;
                *(unsigned*)&olo[i1] = lo1;
            }
        } else {
            *(float2*)&of32[(size_t)r0 * 512 + n] = make_float2(v00, v01);
            *(float2*)&of32[(size_t)r1 * 512 + n] = make_float2(v10, v11);
        }
    }
}

// ---------------------------------------------------------------------------
// Tensor-core flash attention. 128 q x 128 kv per iter, 8 warps.
// Fragments via ldmatrix; V stored row-major, loaded with ldmatrix.trans.
// ---------------------------------------------------------------------------
__global__ __launch_bounds__(256, 1) void attn_mma(
    const bf* __restrict__ qhi, const bf* __restrict__ qlo,
    const bf* __restrict__ khi, const bf* __restrict__ klo,
    const bf* __restrict__ vhi, const bf* __restrict__ vlo,
    const float* __restrict__ mask, float* __restrict__ out)
{
    extern __shared__ char smc[];
    bf* Khi = (bf*)smc;                 // [128][KPITCH]
    bf* Klo = Khi + 128 * KPITCH;
    bf* Vhi = Klo + 128 * KPITCH;       // row-major [kv][dim]
    bf* Vlo = Vhi + 128 * KPITCH;
    float* Ms = (float*)(Vlo + 128 * KPITCH);  // [128]

    const int tid  = threadIdx.x;
    const int warp = tid >> 5;
    const int lane = tid & 31;
    const int g    = lane >> 2;     // 0..7
    const int tg   = lane & 3;      // 0..3
    const int q0   = blockIdx.x * TQ;
    const int h    = blockIdx.y;
    const int b    = blockIdx.z;

    // ldmatrix per-lane address bases
    const int mat = lane >> 3, r8 = lane & 7;
    // K (non-trans): mat0/1 -> t even cols 0/8; mat2/3 -> t odd cols 0/8
    const unsigned k_off = (((mat >> 1) * 8 + r8) * KPITCH + (mat & 1) * 8) * 2;
    // V (trans): mat0/1 -> t even k rows 0-7/8-15; mat2/3 -> t odd
    const unsigned v_off = (((mat & 1) * 8 + r8) * KPITCH + (mat >> 1) * 8) * 2;
    const unsigned khi_b = sm_u32(Khi) + k_off;
    const unsigned klo_b = sm_u32(Klo) + k_off;
    const unsigned vhi_b = sm_u32(Vhi) + v_off;
    const unsigned vlo_b = sm_u32(Vlo) + v_off;

    const size_t base = ((size_t)b * HH + h) * SS * DH;
    const bf* qh = qhi + base;
    const bf* ql = qlo + base;
    const bf* kh = khi + base;
    const bf* kl = klo + base;
    const bf* vh = vhi + base;
    const bf* vl = vlo + base;

    // ---- Q fragments in registers (rows r0=q0+16w+g, r1=r0+8) ----
    unsigned qah[4][4], qal[4][4];
    {
        const int r0 = q0 + warp * 16 + g;
        const int r1 = r0 + 8;
#pragma unroll
        for (int kc = 0; kc < 4; ++kc) {
            int c = kc * 16 + 2 * tg;
            qah[kc][0] = *(const unsigned*)&qh[(size_t)r0 * DH + c];
            qah[kc][1] = *(const unsigned*)&qh[(size_t)r1 * DH + c];
            qah[kc][2] = *(const unsigned*)&qh[(size_t)r0 * DH + c + 8];
            qah[kc][3] = *(const unsigned*)&qh[(size_t)r1 * DH + c + 8];
            qal[kc][0] = *(const unsigned*)&ql[(size_t)r0 * DH + c];
            qal[kc][1] = *(const unsigned*)&ql[(size_t)r1 * DH + c];
            qal[kc][2] = *(const unsigned*)&ql[(size_t)r0 * DH + c + 8];
            qal[kc][3] = *(const unsigned*)&ql[(size_t)r1 * DH + c + 8];
        }
    }

    float oacc[8][4];
#pragma unroll
    for (int t = 0; t < 8; ++t)
#pragma unroll
        for (int i = 0; i < 4; ++i) oacc[t][i] = 0.f;
    float m_a = -1e30f, m_b = -1e30f, l_a = 0.f, l_b = 0.f;

    for (int kt = 0; kt < SS; kt += TK) {
        __syncthreads();
        // ---- stage K and V tiles (both row-major, all uint4) ----
        {
            const int srow = tid >> 1;
            const int scol = (tid & 1) * 32;
            const size_t gro = (size_t)(kt + srow) * DH + scol;
            const int so = srow * KPITCH + scol;
#pragma unroll
            for (int i = 0; i < 4; ++i) {
                *(uint4*)&Khi[so + 8 * i] = *(const uint4*)&kh[gro + 8 * i];
                *(uint4*)&Klo[so + 8 * i] = *(const uint4*)&kl[gro + 8 * i];
                *(uint4*)&Vhi[so + 8 * i] = *(const uint4*)&vh[gro + 8 * i];
                *(uint4*)&Vlo[so + 8 * i] = *(const uint4*)&vl[gro + 8 * i];
            }
            if (tid < TK) Ms[tid] = mask[(size_t)b * SS + kt + tid];
        }
        __syncthreads();

        // ---- S = Q K^T : ldmatrix K frags, 3-term split MMAs ----
        float sacc[16][4];
#pragma unroll
        for (int t = 0; t < 16; ++t)
#pragma unroll
            for (int i = 0; i < 4; ++i) sacc[t][i] = 0.f;

#pragma unroll
        for (int kc = 0; kc < 4; ++kc) {
#pragma unroll
            for (int tp = 0; tp < 8; ++tp) {
                const unsigned off = (tp * 16 * KPITCH + kc * 16) * 2;
                unsigned h0, h1, h2, h3, l0, l1, l2, l3;
                ldsm_x4(khi_b + off, h0, h1, h2, h3);
                ldsm_x4(klo_b + off, l0, l1, l2, l3);
                mma_bf16(sacc[2 * tp],     qah[kc], h0, h1);
                mma_bf16(sacc[2 * tp],     qah[kc], l0, l1);
                mma_bf16(sacc[2 * tp],     qal[kc], h0, h1);
                mma_bf16(sacc[2 * tp + 1], qah[kc], h2, h3);
                mma_bf16(sacc[2 * tp + 1], qah[kc], l2, l3);
                mma_bf16(sacc[2 * tp + 1], qal[kc], h2, h3);
            }
        }

        // ---- mask + row max ----
        float mloc_a = -1e30f, mloc_b = -1e30f;
#pragma unroll
        for (int t = 0; t < 16; ++t) {
            float2 mv = *(const float2*)&Ms[8 * t + 2 * tg];
            float m0 = mv.x * -1e9f, m1 = mv.y * -1e9f;
            sacc[t][0] += m0; sacc[t][1] += m1;
            sacc[t][2] += m0; sacc[t][3] += m1;
            mloc_a = fmaxf(mloc_a, fmaxf(sacc[t][0], sacc[t][1]));
            mloc_b = fmaxf(mloc_b, fmaxf(sacc[t][2], sacc[t][3]));
        }
#pragma unroll
        for (int off = 1; off < 4; off <<= 1) {
            mloc_a = fmaxf(mloc_a, __shfl_xor_sync(0xffffffffu, mloc_a, off));
            mloc_b = fmaxf(mloc_b, __shfl_xor_sync(0xffffffffu, mloc_b, off));
        }
        float mn_a = fmaxf(m_a, mloc_a);
        float mn_b = fmaxf(m_b, mloc_b);
        float corr_a = __expf(m_a - mn_a);
        float corr_b = __expf(m_b - mn_b);
        m_a = mn_a; m_b = mn_b;

        // ---- exp + row sum ----
        float rs_a = 0.f, rs_b = 0.f;
#pragma unroll
        for (int t = 0; t < 16; ++t) {
            sacc[t][0] = __expf(sacc[t][0] - m_a);
            sacc[t][1] = __expf(sacc[t][1] - m_a);
            sacc[t][2] = __expf(sacc[t][2] - m_b);
            sacc[t][3] = __expf(sacc[t][3] - m_b);
            rs_a += sacc[t][0] + sacc[t][1];
            rs_b += sacc[t][2] + sacc[t][3];
        }
#pragma unroll
        for (int off = 1; off < 4; off <<= 1) {
            rs_a += __shfl_xor_sync(0xffffffffu, rs_a, off);
            rs_b += __shfl_xor_sync(0xffffffffu, rs_b, off);
        }
        l_a = l_a * corr_a + rs_a;
        l_b = l_b * corr_b + rs_b;
#pragma unroll
        for (int t = 0; t < 8; ++t) {
            oacc[t][0] *= corr_a; oacc[t][1] *= corr_a;
            oacc[t][2] *= corr_b; oacc[t][3] *= corr_b;
        }

        // ---- O += P V : pack P, ldmatrix.trans V frags ----
#pragma unroll
        for (int kc = 0; kc < 8; ++kc) {
            unsigned pah[4], pal[4];
#pragma unroll
            for (int half = 0; half < 2; ++half) {
                const float* s4 = sacc[2 * kc + half];
                bf h0 = __float2bfloat16_rn(s4[0]);
                bf h1 = __float2bfloat16_rn(s4[1]);
                bf h2 = __float2bfloat16_rn(s4[2]);
                bf h3 = __float2bfloat16_rn(s4[3]);
                pah[2 * half + 0] = pack_bf2(h0, h1);
                pah[2 * half + 1] = pack_bf2(h2, h3);
                pal[2 * half + 0] = pack_bf2(
                    __float2bfloat16_rn(s4[0] - __bfloat162float(h0)),
                    __float2bfloat16_rn(s4[1] - __bfloat162float(h1)));
                pal[2 * half + 1] = pack_bf2(
                    __float2bfloat16_rn(s4[2] - __bfloat162float(h2)),
                    __float2bfloat16_rn(s4[3] - __bfloat162float(h3)));
            }
#pragma unroll
            for (int np = 0; np < 4; ++np) {
                const unsigned off = (kc * 16 * KPITCH + np * 16) * 2;
                unsigned h0, h1, h2, h3, l0, l1, l2, l3;
                ldsm_x4_t(vhi_b + off, h0, h1, h2, h3);
                ldsm_x4_t(vlo_b + off, l0, l1, l2, l3);
                mma_bf16(oacc[2 * np],     pah, h0, h1);
                mma_bf16(oacc[2 * np],     pah, l0, l1);
                mma_bf16(oacc[2 * np],     pal, h0, h1);
                mma_bf16(oacc[2 * np + 1], pah, h2, h3);
                mma_bf16(oacc[2 * np + 1], pah, l2, l3);
                mma_bf16(oacc[2 * np + 1], pal, h2, h3);
            }
        }
    }

    // ---- epilogue: normalize, write merged-head [B,S,D] fp32 ----
    {
        float inva = 1.0f / l_a, invb = 1.0f / l_b;
        const int r0 = q0 + warp * 16 + g;
        const int r1 = r0 + 8;
#pragma unroll
        for (int t = 0; t < 8; ++t) {
            int c = h * DH + 8 * t + 2 * tg;
            float2 va = {oacc[t][0] * inva, oacc[t][1] * inva};
            float2 vb = {oacc[t][2] * invb, oacc[t][3] * invb};
            *(float2*)&out[((size_t)b * SS + r0) * DD + c] = va;
            *(float2*)&out[((size_t)b * SS + r1) * DD + c] = vb;
        }
    }
}

// ---------------------------------------------------------------------------
extern "C" void kernel_launch(void* const* d_in, const int* in_sizes, int n_in,
                              void* d_out, int out_size)
{
    (void)in_sizes; (void)n_in; (void)out_size;
    const float* q    = (const float*)d_in[0];
    const float* k    = (const float*)d_in[1];
    const float* v    = (const float*)d_in[2];
    const float* mask = (const float*)d_in[3];
    const float* wq   = (const float*)d_in[4];
    const float* bq   = (const float*)d_in[5];
    const float* wk   = (const float*)d_in[6];
    const float* bk   = (const float*)d_in[7];
    const float* wv   = (const float*)d_in[8];
    const float* bv   = (const float*)d_in[9];
    const float* wo   = (const float*)d_in[10];
    const float* bo   = (const float*)d_in[11];
    float* out = (float*)d_out;

    bf *qhi, *qlo, *khi, *klo, *vhi, *vlo;
    float* attn;
    cudaGetSymbolAddress((void**)&qhi, g_qhi);
    cudaGetSymbolAddress((void**)&qlo, g_qlo);
    cudaGetSymbolAddress((void**)&khi, g_khi);
    cudaGetSymbolAddress((void**)&klo, g_klo);
    cudaGetSymbolAddress((void**)&vhi, g_vhi);
    cudaGetSymbolAddress((void**)&vlo, g_vlo);
    cudaGetSymbolAddress((void**)&attn, g_attn);

    const int ATTN_SMEM = 4 * 128 * KPITCH * 2 + 128 * 4;  // 74240 B
    static int smem_set = 0;
    if (!smem_set) {
        cudaFuncSetAttribute(attn_mma,
                             cudaFuncAttributeMaxDynamicSharedMemorySize,
                             ATTN_SMEM);
        smem_set = 1;
    }

    dim3 gproj(DD / 128, M_ROWS / 128);  // (4, 64)
    proj_mma<0><<<gproj, 256>>>(q, wq, bq, qhi, qlo, nullptr);
    proj_mma<0><<<gproj, 256>>>(k, wk, bk, khi, klo, nullptr);
    proj_mma<0><<<gproj, 256>>>(v, wv, bv, vhi, vlo, nullptr);

    dim3 gattn(SS / TQ, HH, BB);       // (32, 8, 2)
    attn_mma<<<gattn, 256, ATTN_SMEM>>>(qhi, qlo, khi, klo, vhi, vlo,
                                        mask, attn);

    proj_mma<1><<<gproj, 256>>>(attn, wo, bo, nullptr, nullptr, out);
}

// round 10
// speedup vs baseline: 4.5426x; 1.0184x over previous
#include <cuda_runtime.h>
#include <cuda_bf16.h>
#include <math.h>

#define BB 2
#define SS 4096
#define DD 512
#define HH 8
#define DH 64
#define M_ROWS (BB*SS)   // 8192

#define TQ 128
#define TK 128
#define KPITCH 72        // K/V smem pitch in bf16 elems (stride 4 banks mod 32)

// per-buffer byte offsets inside the double-buffered staging region
#define REG_BYTES  (128 * KPITCH * 2)          // one [128][KPITCH] bf16 array
#define OFF_KHI    0
#define OFF_KLO    (REG_BYTES)
#define OFF_VHI    (2 * REG_BYTES)
#define OFF_VLO    (3 * REG_BYTES)
#define OFF_MS     (4 * REG_BYTES)             // 128 floats
#define BUF_BYTES  (4 * REG_BYTES + 512)       // 74240 B per buffer

typedef __nv_bfloat16 bf;

// Scratch (allocation-free rule: __device__ globals). [B,H,S,d] layout.
__device__ bf g_qhi[(size_t)BB*HH*SS*DH];
__device__ bf g_qlo[(size_t)BB*HH*SS*DH];
__device__ bf g_khi[(size_t)BB*HH*SS*DH];
__device__ bf g_klo[(size_t)BB*HH*SS*DH];
__device__ bf g_vhi[(size_t)BB*HH*SS*DH];
__device__ bf g_vlo[(size_t)BB*HH*SS*DH];
__device__ float g_attn[(size_t)M_ROWS*DD];   // [B*S, D]

__device__ __forceinline__ void mma_bf16(float* c, const unsigned* a,
                                         unsigned b0, unsigned b1)
{
    asm("mma.sync.aligned.m16n8k16.row.col.f32.bf16.bf16.f32 "
        "{%0,%1,%2,%3},{%4,%5,%6,%7},{%8,%9},{%0,%1,%2,%3};"
        : "+f"(c[0]), "+f"(c[1]), "+f"(c[2]), "+f"(c[3])
        : "r"(a[0]), "r"(a[1]), "r"(a[2]), "r"(a[3]), "r"(b0), "r"(b1));
}

__device__ __forceinline__ unsigned pack_bf2(bf a, bf b)
{
    __nv_bfloat162 t = __halves2bfloat162(a, b);   // a -> low, b -> high
    return *(unsigned*)&t;
}

__device__ __forceinline__ void split2(float x, float y,
                                       unsigned& hi, unsigned& lo)
{
    bf hx = __float2bfloat16_rn(x), hy = __float2bfloat16_rn(y);
    hi = pack_bf2(hx, hy);
    lo = pack_bf2(__float2bfloat16_rn(x - __bfloat162float(hx)),
                  __float2bfloat16_rn(y - __bfloat162float(hy)));
}

__device__ __forceinline__ unsigned sm_u32(const void* p)
{
    return (unsigned)__cvta_generic_to_shared(p);
}

__device__ __forceinline__ void ldsm_x4(unsigned addr, unsigned& r0,
                                        unsigned& r1, unsigned& r2, unsigned& r3)
{
    asm volatile("ldmatrix.sync.aligned.m8n8.x4.shared.b16 {%0,%1,%2,%3},[%4];"
                 : "=r"(r0), "=r"(r1), "=r"(r2), "=r"(r3) : "r"(addr));
}

__device__ __forceinline__ void ldsm_x4_t(unsigned addr, unsigned& r0,
                                          unsigned& r1, unsigned& r2, unsigned& r3)
{
    asm volatile("ldmatrix.sync.aligned.m8n8.x4.trans.shared.b16 {%0,%1,%2,%3},[%4];"
                 : "=r"(r0), "=r"(r1), "=r"(r2), "=r"(r3) : "r"(addr));
}

__device__ __forceinline__ void cpa16(unsigned saddr, const void* gaddr)
{
    asm volatile("cp.async.cg.shared.global [%0], [%1], 16;\n"
                 :: "r"(saddr), "l"(gaddr));
}

__device__ __forceinline__ void cpa_commit()
{
    asm volatile("cp.async.commit_group;\n" ::: "memory");
}

__device__ __forceinline__ void cpa_wait_all()
{
    asm volatile("cp.async.wait_group 0;\n" ::: "memory");
}

// ---------------------------------------------------------------------------
// Tensor-core projection GEMM: out = A[8192 x 512] @ W[512 x 512] + bias.
// CTA = 128x128, BK=16 double-buffered. 8 warps, warp w: m-rows [16w,16w+16).
// MODE 0: scatter hi/lo bf16 into [B,H,S,d].  MODE 1: fp32 row-major.
// ---------------------------------------------------------------------------
template<int MODE>
__global__ __launch_bounds__(256, 2) void proj_mma(
    const float* __restrict__ A, const float* __restrict__ W,
    const float* __restrict__ bias,
    bf* __restrict__ ohi, bf* __restrict__ olo, float* __restrict__ of32)
{
    __shared__ bf Ah[2][128*16], Al[2][128*16];
    __shared__ bf Wh[2][128*16], Wl[2][128*16];

    const int tid  = threadIdx.x;
    const int warp = tid >> 5, lane = tid & 31;
    const int g = lane >> 2, tg = lane & 3;
    const int n0 = blockIdx.x * 128;
    const int m0 = blockIdx.y * 128;

    const int sm  = tid >> 1;            // A: row 0..127
    const int skk = (tid & 1) * 8;       // A: k offset 0/8
    const int wkk = tid & 15;            // W: k 0..15
    const int wn8 = (tid >> 4) * 8;      // W: n offset 0..120

    float acc[16][4];
#pragma unroll
    for (int t = 0; t < 16; ++t)
#pragma unroll
        for (int i = 0; i < 4; ++i) acc[t][i] = 0.f;

    // ---- stage chunk 0 into buffer 0 ----
    {
        const float* Ap = A + (size_t)(m0 + sm) * 512 + skk;
        float4 u1 = *(const float4*)Ap;
        float4 u2 = *(const float4*)(Ap + 4);
        unsigned h0, l0, h1, l1, h2, l2, h3, l3;
        split2(u1.x, u1.y, h0, l0); split2(u1.z, u1.w, h1, l1);
        split2(u2.x, u2.y, h2, l2); split2(u2.z, u2.w, h3, l3);
        *(uint4*)&Ah[0][sm * 16 + skk] = make_uint4(h0, h1, h2, h3);
        *(uint4*)&Al[0][sm * 16 + skk] = make_uint4(l0, l1, l2, l3);

        const float* Wp = W + (size_t)wkk * 512 + n0 + wn8;
        float4 w1 = *(const float4*)Wp;
        float4 w2 = *(const float4*)(Wp + 4);
        float wv[8] = {w1.x, w1.y, w1.z, w1.w, w2.x, w2.y, w2.z, w2.w};
#pragma unroll
        for (int j = 0; j < 8; ++j) {
            bf h = __float2bfloat16_rn(wv[j]);
            Wh[0][(wn8 + j) * 16 + wkk] = h;
            Wl[0][(wn8 + j) * 16 + wkk] =
                __float2bfloat16_rn(wv[j] - __bfloat162float(h));
        }
    }
    __syncthreads();

#pragma unroll 1
    for (int c = 0; c < 32; ++c) {
        const int cur = c & 1;
        if (c + 1 < 32) {
            const int nxt = (c + 1) & 1;
            const int k0 = (c + 1) * 16;
            const float* Ap = A + (size_t)(m0 + sm) * 512 + k0 + skk;
            float4 u1 = *(const float4*)Ap;
            float4 u2 = *(const float4*)(Ap + 4);
            unsigned h0, l0, h1, l1, h2, l2, h3, l3;
            split2(u1.x, u1.y, h0, l0); split2(u1.z, u1.w, h1, l1);
            split2(u2.x, u2.y, h2, l2); split2(u2.z, u2.w, h3, l3);
            *(uint4*)&Ah[nxt][sm * 16 + skk] = make_uint4(h0, h1, h2, h3);
            *(uint4*)&Al[nxt][sm * 16 + skk] = make_uint4(l0, l1, l2, l3);

            const float* Wp = W + (size_t)(k0 + wkk) * 512 + n0 + wn8;
            float4 w1 = *(const float4*)Wp;
            float4 w2 = *(const float4*)(Wp + 4);
            float wv[8] = {w1.x, w1.y, w1.z, w1.w, w2.x, w2.y, w2.z, w2.w};
#pragma unroll
            for (int j = 0; j < 8; ++j) {
                bf h = __float2bfloat16_rn(wv[j]);
                Wh[nxt][(wn8 + j) * 16 + wkk] = h;
                Wl[nxt][(wn8 + j) * 16 + wkk] =
                    __float2bfloat16_rn(wv[j] - __bfloat162float(h));
            }
        }

        {
            const int arow = warp * 16 + g;
            unsigned ah[4], al[4];
            ah[0] = *(const unsigned*)&Ah[cur][arow * 16 + 2 * tg];
            ah[1] = *(const unsigned*)&Ah[cur][(arow + 8) * 16 + 2 * tg];
            ah[2] = *(const unsigned*)&Ah[cur][arow * 16 + 2 * tg + 8];
            ah[3] = *(const unsigned*)&Ah[cur][(arow + 8) * 16 + 2 * tg + 8];
            al[0] = *(const unsigned*)&Al[cur][arow * 16 + 2 * tg];
            al[1] = *(const unsigned*)&Al[cur][(arow + 8) * 16 + 2 * tg];
            al[2] = *(const unsigned*)&Al[cur][arow * 16 + 2 * tg + 8];
            al[3] = *(const unsigned*)&Al[cur][(arow + 8) * 16 + 2 * tg + 8];
#pragma unroll
            for (int t = 0; t < 16; ++t) {
                const int n = 8 * t + g;
                unsigned bh0 = *(const unsigned*)&Wh[cur][n * 16 + 2 * tg];
                unsigned bh1 = *(const unsigned*)&Wh[cur][n * 16 + 2 * tg + 8];
                unsigned bl0 = *(const unsigned*)&Wl[cur][n * 16 + 2 * tg];
                unsigned bl1 = *(const unsigned*)&Wl[cur][n * 16 + 2 * tg + 8];
                mma_bf16(acc[t], ah, bh0, bh1);
                mma_bf16(acc[t], ah, bl0, bl1);
                mma_bf16(acc[t], al, bh0, bh1);
            }
        }
        __syncthreads();
    }

    // ---- epilogue ----
    const int r0 = m0 + warp * 16 + g;
    const int r1 = r0 + 8;
#pragma unroll
    for (int t = 0; t < 16; ++t) {
        const int n = n0 + 8 * t + 2 * tg;
        float2 bv = *(const float2*)&bias[n];
        float v00 = acc[t][0] + bv.x, v01 = acc[t][1] + bv.y;  // row r0
        float v10 = acc[t][2] + bv.x, v11 = acc[t][3] + bv.y;  // row r1
        if (MODE == 0) {
            const int h = n >> 6, dd = n & 63;
            unsigned hi0, lo0, hi1, lo1;
            split2(v00, v01, hi0, lo0);
            split2(v10, v11, hi1, lo1);
            {
                int b = r0 >> 12, s = r0 & 4095;
                size_t i0 = (((size_t)b * HH + h) * SS + s) * DH + dd;
                *(unsigned*)&ohi[i0] = hi0;
                *(unsigned*)&olo[i0] = lo0;
            }
            {
                int b = r1 >> 12, s = r1 & 4095;
                size_t i1 = (((size_t)b * HH + h) * SS + s) * DH + dd;
                *(unsigned*)&ohi[i1] = hi1;
                *(unsigned*)&olo[i1] = lo1;
            }
        } else {
            *(float2*)&of32[(size_t)r0 * 512 + n] = make_float2(v00, v01);
            *(float2*)&of32[(size_t)r1 * 512 + n] = make_float2(v10, v11);
        }
    }
}

// ---------------------------------------------------------------------------
// Tensor-core flash attention. 128 q x 128 kv per iter, 8 warps.
// cp.async double-buffered K/V staging; ldmatrix fragments; 3-term split MMAs.
// ---------------------------------------------------------------------------
__global__ __launch_bounds__(256, 1) void attn_mma(
    const bf* __restrict__ qhi, const bf* __restrict__ qlo,
    const bf* __restrict__ khi, const bf* __restrict__ klo,
    const bf* __restrict__ vhi, const bf* __restrict__ vlo,
    const float* __restrict__ mask, float* __restrict__ out)
{
    extern __shared__ char smc[];
    const unsigned smb = sm_u32(smc);

    const int tid  = threadIdx.x;
    const int warp = tid >> 5;
    const int lane = tid & 31;
    const int g    = lane >> 2;     // 0..7
    const int tg   = lane & 3;      // 0..3
    const int q0   = blockIdx.x * TQ;
    const int h    = blockIdx.y;
    const int b    = blockIdx.z;

    // ldmatrix per-lane address offsets (within one [128][KPITCH] region)
    const int mat = lane >> 3, r8 = lane & 7;
    const unsigned k_off = (((mat >> 1) * 8 + r8) * KPITCH + (mat & 1) * 8) * 2;
    const unsigned v_off = (((mat & 1) * 8 + r8) * KPITCH + (mat >> 1) * 8) * 2;

    const size_t base = ((size_t)b * HH + h) * SS * DH;
    const bf* qh = qhi + base;
    const bf* ql = qlo + base;
    const bf* kh = khi + base;
    const bf* kl = klo + base;
    const bf* vh = vhi + base;
    const bf* vl = vlo + base;
    const float* mb = mask + (size_t)b * SS;

    // staging indices
    const int srow = tid >> 1;
    const int scol = (tid & 1) * 32;
    const unsigned sobyte = (srow * KPITCH + scol) * 2;

    // ---- Q fragments in registers (rows r0=q0+16w+g, r1=r0+8) ----
    unsigned qah[4][4], qal[4][4];
    {
        const int r0 = q0 + warp * 16 + g;
        const int r1 = r0 + 8;
#pragma unroll
        for (int kc = 0; kc < 4; ++kc) {
            int c = kc * 16 + 2 * tg;
            qah[kc][0] = *(const unsigned*)&qh[(size_t)r0 * DH + c];
            qah[kc][1] = *(const unsigned*)&qh[(size_t)r1 * DH + c];
            qah[kc][2] = *(const unsigned*)&qh[(size_t)r0 * DH + c + 8];
            qah[kc][3] = *(const unsigned*)&qh[(size_t)r1 * DH + c + 8];
            qal[kc][0] = *(const unsigned*)&ql[(size_t)r0 * DH + c];
            qal[kc][1] = *(const unsigned*)&ql[(size_t)r1 * DH + c];
            qal[kc][2] = *(const unsigned*)&ql[(size_t)r0 * DH + c + 8];
            qal[kc][3] = *(const unsigned*)&ql[(size_t)r1 * DH + c + 8];
        }
    }

    float oacc[8][4];
#pragma unroll
    for (int t = 0; t < 8; ++t)
#pragma unroll
        for (int i = 0; i < 4; ++i) oacc[t][i] = 0.f;
    float m_a = -1e30f, m_b = -1e30f, l_a = 0.f, l_b = 0.f;

    // ---- prologue: stage tile 0 into buffer 0 ----
    {
        const unsigned bufb = smb;
        const size_t gro = (size_t)srow * DH + scol;
#pragma unroll
        for (int i = 0; i < 4; ++i) {
            cpa16(bufb + OFF_KHI + sobyte + 16 * i, &kh[gro + 8 * i]);
            cpa16(bufb + OFF_KLO + sobyte + 16 * i, &kl[gro + 8 * i]);
            cpa16(bufb + OFF_VHI + sobyte + 16 * i, &vh[gro + 8 * i]);
            cpa16(bufb + OFF_VLO + sobyte + 16 * i, &vl[gro + 8 * i]);
        }
        if (tid < 32) cpa16(bufb + OFF_MS + tid * 16, &mb[tid * 4]);
        cpa_commit();
    }

#pragma unroll 1
    for (int kt = 0; kt < SS; kt += TK) {
        const int cur = (kt >> 7) & 1;
        const unsigned bufb = smb + cur * BUF_BYTES;

        cpa_wait_all();      // buffer cur's group complete (thread-local)
        __syncthreads();     // all threads' stages visible; prev iter's reads done

        // ---- prefetch tile kt+TK into the other buffer ----
        if (kt + TK < SS) {
            const unsigned nbufb = smb + (cur ^ 1) * BUF_BYTES;
            const size_t gro = (size_t)(kt + TK + srow) * DH + scol;
#pragma unroll
            for (int i = 0; i < 4; ++i) {
                cpa16(nbufb + OFF_KHI + sobyte + 16 * i, &kh[gro + 8 * i]);
                cpa16(nbufb + OFF_KLO + sobyte + 16 * i, &kl[gro + 8 * i]);
                cpa16(nbufb + OFF_VHI + sobyte + 16 * i, &vh[gro + 8 * i]);
                cpa16(nbufb + OFF_VLO + sobyte + 16 * i, &vl[gro + 8 * i]);
            }
            if (tid < 32) cpa16(nbufb + OFF_MS + tid * 16, &mb[kt + TK + tid * 4]);
            cpa_commit();
        }

        const unsigned khi_b = bufb + OFF_KHI + k_off;
        const unsigned klo_b = bufb + OFF_KLO + k_off;
        const unsigned vhi_b = bufb + OFF_VHI + v_off;
        const unsigned vlo_b = bufb + OFF_VLO + v_off;
        const float* Ms = (const float*)(smc + cur * BUF_BYTES + OFF_MS);

        // ---- S = Q K^T : ldmatrix K frags, 3-term split MMAs ----
        float sacc[16][4];
#pragma unroll
        for (int t = 0; t < 16; ++t)
#pragma unroll
            for (int i = 0; i < 4; ++i) sacc[t][i] = 0.f;

#pragma unroll
        for (int kc = 0; kc < 4; ++kc) {
#pragma unroll
            for (int tp = 0; tp < 8; ++tp) {
                const unsigned off = (tp * 16 * KPITCH + kc * 16) * 2;
                unsigned h0, h1, h2, h3, l0, l1, l2, l3;
                ldsm_x4(khi_b + off, h0, h1, h2, h3);
                ldsm_x4(klo_b + off, l0, l1, l2, l3);
                mma_bf16(sacc[2 * tp],     qah[kc], h0, h1);
                mma_bf16(sacc[2 * tp],     qah[kc], l0, l1);
                mma_bf16(sacc[2 * tp],     qal[kc], h0, h1);
                mma_bf16(sacc[2 * tp + 1], qah[kc], h2, h3);
                mma_bf16(sacc[2 * tp + 1], qah[kc], l2, l3);
                mma_bf16(sacc[2 * tp + 1], qal[kc], h2, h3);
            }
        }

        // ---- mask + row max ----
        float mloc_a = -1e30f, mloc_b = -1e30f;
#pragma unroll
        for (int t = 0; t < 16; ++t) {
            float2 mv = *(const float2*)&Ms[8 * t + 2 * tg];
            float m0 = mv.x * -1e9f, m1 = mv.y * -1e9f;
            sacc[t][0] += m0; sacc[t][1] += m1;
            sacc[t][2] += m0; sacc[t][3] += m1;
            mloc_a = fmaxf(mloc_a, fmaxf(sacc[t][0], sacc[t][1]));
            mloc_b = fmaxf(mloc_b, fmaxf(sacc[t][2], sacc[t][3]));
        }
#pragma unroll
        for (int off = 1; off < 4; off <<= 1) {
            mloc_a = fmaxf(mloc_a, __shfl_xor_sync(0xffffffffu, mloc_a, off));
            mloc_b = fmaxf(mloc_b, __shfl_xor_sync(0xffffffffu, mloc_b, off));
        }
        float mn_a = fmaxf(m_a, mloc_a);
        float mn_b = fmaxf(m_b, mloc_b);
        float corr_a = __expf(m_a - mn_a);
        float corr_b = __expf(m_b - mn_b);
        m_a = mn_a; m_b = mn_b;

        // ---- exp + row sum ----
        float rs_a = 0.f, rs_b = 0.f;
#pragma unroll
        for (int t = 0; t < 16; ++t) {
            sacc[t][0] = __expf(sacc[t][0] - m_a);
            sacc[t][1] = __expf(sacc[t][1] - m_a);
            sacc[t][2] = __expf(sacc[t][2] - m_b);
            sacc[t][3] = __expf(sacc[t][3] - m_b);
            rs_a += sacc[t][0] + sacc[t][1];
            rs_b += sacc[t][2] + sacc[t][3];
        }
#pragma unroll
        for (int off = 1; off < 4; off <<= 1) {
            rs_a += __shfl_xor_sync(0xffffffffu, rs_a, off);
            rs_b += __shfl_xor_sync(0xffffffffu, rs_b, off);
        }
        l_a = l_a * corr_a + rs_a;
        l_b = l_b * corr_b + rs_b;
#pragma unroll
        for (int t = 0; t < 8; ++t) {
            oacc[t][0] *= corr_a; oacc[t][1] *= corr_a;
            oacc[t][2] *= corr_b; oacc[t][3] *= corr_b;
        }

        // ---- O += P V : pack P, ldmatrix.trans V frags ----
#pragma unroll
        for (int kc = 0; kc < 8; ++kc) {
            unsigned pah[4], pal[4];
#pragma unroll
            for (int half = 0; half < 2; ++half) {
                const float* s4 = sacc[2 * kc + half];
                bf h0 = __float2bfloat16_rn(s4[0]);
                bf h1 = __float2bfloat16_rn(s4[1]);
                bf h2 = __float2bfloat16_rn(s4[2]);
                bf h3 = __float2bfloat16_rn(s4[3]);
                pah[2 * half + 0] = pack_bf2(h0, h1);
                pah[2 * half + 1] = pack_bf2(h2, h3);
                pal[2 * half + 0] = pack_bf2(
                    __float2bfloat16_rn(s4[0] - __bfloat162float(h0)),
                    __float2bfloat16_rn(s4[1] - __bfloat162float(h1)));
                pal[2 * half + 1] = pack_bf2(
                    __float2bfloat16_rn(s4[2] - __bfloat162float(h2)),
                    __float2bfloat16_rn(s4[3] - __bfloat162float(h3)));
            }
#pragma unroll
            for (int np = 0; np < 4; ++np) {
                const unsigned off = (kc * 16 * KPITCH + np * 16) * 2;
                unsigned h0, h1, h2, h3, l0, l1, l2, l3;
                ldsm_x4_t(vhi_b + off, h0, h1, h2, h3);
                ldsm_x4_t(vlo_b + off, l0, l1, l2, l3);
                mma_bf16(oacc[2 * np],     pah, h0, h1);
                mma_bf16(oacc[2 * np],     pah, l0, l1);
                mma_bf16(oacc[2 * np],     pal, h0, h1);
                mma_bf16(oacc[2 * np + 1], pah, h2, h3);
                mma_bf16(oacc[2 * np + 1], pah, l2, l3);
                mma_bf16(oacc[2 * np + 1], pal, h2, h3);
            }
        }
    }

    // ---- epilogue: normalize, write merged-head [B,S,D] fp32 ----
    {
        float inva = 1.0f / l_a, invb = 1.0f / l_b;
        const int r0 = q0 + warp * 16 + g;
        const int r1 = r0 + 8;
#pragma unroll
        for (int t = 0; t < 8; ++t) {
            int c = h * DH + 8 * t + 2 * tg;
            float2 va = {oacc[t][0] * inva, oacc[t][1] * inva};
            float2 vb = {oacc[t][2] * invb, oacc[t][3] * invb};
            *(float2*)&out[((size_t)b * SS + r0) * DD + c] = va;
            *(float2*)&out[((size_t)b * SS + r1) * DD + c] = vb;
        }
    }
}

// ---------------------------------------------------------------------------
extern "C" void kernel_launch(void* const* d_in, const int* in_sizes, int n_in,
                              void* d_out, int out_size)
{
    (void)in_sizes; (void)n_in; (void)out_size;
    const float* q    = (const float*)d_in[0];
    const float* k    = (const float*)d_in[1];
    const float* v    = (const float*)d_in[2];
    const float* mask = (const float*)d_in[3];
    const float* wq   = (const float*)d_in[4];
    const float* bq   = (const float*)d_in[5];
    const float* wk   = (const float*)d_in[6];
    const float* bk   = (const float*)d_in[7];
    const float* wv   = (const float*)d_in[8];
    const float* bv   = (const float*)d_in[9];
    const float* wo   = (const float*)d_in[10];
    const float* bo   = (const float*)d_in[11];
    float* out = (float*)d_out;

    bf *qhi, *qlo, *khi, *klo, *vhi, *vlo;
    float* attn;
    cudaGetSymbolAddress((void**)&qhi, g_qhi);
    cudaGetSymbolAddress((void**)&qlo, g_qlo);
    cudaGetSymbolAddress((void**)&khi, g_khi);
    cudaGetSymbolAddress((void**)&klo, g_klo);
    cudaGetSymbolAddress((void**)&vhi, g_vhi);
    cudaGetSymbolAddress((void**)&vlo, g_vlo);
    cudaGetSymbolAddress((void**)&attn, g_attn);

    const int ATTN_SMEM = 2 * BUF_BYTES;  // 148480 B
    static int smem_set = 0;
    if (!smem_set) {
        cudaFuncSetAttribute(attn_mma,
                             cudaFuncAttributeMaxDynamicSharedMemorySize,
                             ATTN_SMEM);
        smem_set = 1;
    }

    dim3 gproj(DD / 128, M_ROWS / 128);  // (4, 64)
    proj_mma<0><<<gproj, 256>>>(q, wq, bq, qhi, qlo, nullptr);
    proj_mma<0><<<gproj, 256>>>(k, wk, bk, khi, klo, nullptr);
    proj_mma<0><<<gproj, 256>>>(v, wv, bv, vhi, vlo, nullptr);

    dim3 gattn(SS / TQ, HH, BB);       // (32, 8, 2)
    attn_mma<<<gattn, 256, ATTN_SMEM>>>(qhi, qlo, khi, klo, vhi, vlo,
                                        mask, attn);

    proj_mma<1><<<gproj, 256>>>(attn, wo, bo, nullptr, nullptr, out);
}